// round 12
// baseline (speedup 1.0000x reference)
#include <cuda_runtime.h>
#include <cuda_fp16.h>
#include <math.h>
#include <stdint.h>

#define BB 2
#define TT 2048
#define DIMM 1024
#define HH 16
#define MM (BB*TT)
#define TKE 1024
#define NCH 16
#define EPSF 1.1920928955078125e-07f
#define GSMEM (3*32768)
#define SMB 50176   /* stageB: 2*16384 (P) + 2*8704 (G) */

__device__ __align__(256) __half g_xs[(size_t)MM * TKE];
__device__ __align__(256) __half g_wkv[(size_t)2048 * TKE];  /* head-interleaved [k_h|v_h] */
__device__ __align__(256) __half g_wo[(size_t)1024 * TKE];
__device__ __align__(256) __half g_loads[(size_t)MM * TKE];
__device__ __align__(256) float g_kv[(size_t)MM * DIMM];
__device__ __align__(256) float g_F[TT * 64];
__device__ __align__(256) float g_G[TT * HH * 64];
__device__ __align__(256) float g_P[BB * HH * 64 * 64];

__device__ __forceinline__ uint32_t smem_u32(const void* p) {
    uint32_t a;
    asm("{ .reg .u64 t; cvta.to.shared.u64 t, %1; cvt.u32.u64 %0, t; }" : "=r"(a) : "l"(p));
    return a;
}
__device__ __forceinline__ void cpa16(uint32_t d, const void* s) {
    asm volatile("cp.async.cg.shared.global [%0], [%1], 16;" :: "r"(d), "l"(s));
}
/* fp32 Cody-Waite 2pi reduction: P1 products exact (n has <=8 mantissa bits) */
__device__ __forceinline__ void sincos_cw(float ang, float* s, float* c) {
    const float INV2PI = 0.15915494309189535f;
    const float P1 = 6.28125f;
    const float P2 = 1.9353071795864769e-3f;
    float n = rintf(ang * INV2PI);
    float r = fmaf(-n, P1, ang);
    r = fmaf(-n, P2, r);
    sincosf(r, s, c);
}
__device__ __forceinline__ void store_h4(__half* dst, float4 v) {
    __half2* d = (__half2*)dst;
    d[0] = __floats2half2_rn(v.x, v.y);
    d[1] = __floats2half2_rn(v.z, v.w);
}
__device__ __forceinline__ uint4 ldsm4(uint32_t a) {
    uint4 r;
    asm volatile("ldmatrix.sync.aligned.m8n8.x4.shared.b16 {%0,%1,%2,%3}, [%4];"
                 : "=r"(r.x), "=r"(r.y), "=r"(r.z), "=r"(r.w) : "r"(a));
    return r;
}
__device__ __forceinline__ void mma16816(float* c, uint4 a, uint32_t b0, uint32_t b1) {
    asm volatile("mma.sync.aligned.m16n8k16.row.col.f32.f16.f16.f32 "
                 "{%0,%1,%2,%3}, {%4,%5,%6,%7}, {%8,%9}, {%0,%1,%2,%3};"
                 : "+f"(c[0]), "+f"(c[1]), "+f"(c[2]), "+f"(c[3])
                 : "r"(a.x), "r"(a.y), "r"(a.z), "r"(a.w), "r"(b0), "r"(b1));
}

/* ---- fused prep: convw (0..3071) | trig (3072..5119) | rmsnorm (5120..9215) | zeroP (9216..9247) ---- */
__global__ void __launch_bounds__(256) k_prep(const float* __restrict__ states,
                                              const float* __restrict__ lnw,
                                              const float* __restrict__ Wk,
                                              const float* __restrict__ Wv,
                                              const float* __restrict__ Wo,
                                              const float* __restrict__ angles,
                                              const float* __restrict__ hdelta) {
    const int bid = blockIdx.x, tid = threadIdx.x;
    if (bid < 3072) {                                   /* weight conversion */
        int row = bid;
        const float* src; __half* dst;
        if (row < 2048) {
            int h = row >> 7, c = row & 127;
            src = (c < 64) ? Wk + (size_t)(h * 64 + c) * 1024
                           : Wv + (size_t)(h * 64 + c - 64) * 1024;
            dst = g_wkv + (size_t)row * TKE;
        } else {
            src = Wo + (size_t)(row - 2048) * 1024;
            dst = g_wo + (size_t)(row - 2048) * TKE;
        }
        float4 v = ((const float4*)src)[tid];
        store_h4(dst + tid * 4, v);
    } else if (bid < 5120) {                            /* trig tables */
        int t = bid - 3072;
        __shared__ float w[32], hd[16];
        if (tid < 32) w[tid] = angles[tid];
        if (tid >= 32 && tid < 48) hd[tid - 32] = hdelta[tid - 32];
        __syncthreads();
        if (tid < 32) {
            float s, c; sincos_cw((float)t * w[tid], &s, &c);
            g_F[t * 64 + tid] = c; g_F[t * 64 + 32 + tid] = s;
        }
        for (int e = tid; e < 512; e += 256) {
            int h = e >> 5, j = e & 31;
            float s, c; sincos_cw(((float)t + hd[h]) * w[j], &s, &c);
            g_G[(size_t)(t * HH + h) * 64 + j]      = c * 0.03125f;
            g_G[(size_t)(t * HH + h) * 64 + 32 + j] = s * 0.03125f;
        }
    } else if (bid < 9216) {                            /* RMSNorm -> fp16 A */
        int row = bid - 5120;
        float4 v = ((const float4*)(states + (size_t)row * DIMM))[tid];
        float ss = v.x*v.x + v.y*v.y + v.z*v.z + v.w*v.w;
        #pragma unroll
        for (int o = 16; o > 0; o >>= 1) ss += __shfl_xor_sync(0xffffffffu, ss, o);
        __shared__ float wsum[8];
        if ((tid & 31) == 0) wsum[tid >> 5] = ss;
        __syncthreads();
        if (tid < 8) {
            float s2 = wsum[tid];
            #pragma unroll
            for (int o = 4; o > 0; o >>= 1) s2 += __shfl_xor_sync(0xffu, s2, o);
            if (tid == 0) wsum[0] = s2;
        }
        __syncthreads();
        float sc = rsqrtf(wsum[0] * (1.0f / DIMM) + EPSF);
        float4 w = ((const float4*)lnw)[tid];
        float4 o = make_float4(v.x*sc*w.x, v.y*sc*w.y, v.z*sc*w.z, v.w*sc*w.w);
        store_h4(g_xs + (size_t)row * TKE + tid * 4, o);
    } else {                                            /* zero g_P: 32 blocks x 4096 floats */
        int base = (bid - 9216) * 4096 + tid * 4;
        float4 z = make_float4(0.f, 0.f, 0.f, 0.f);
        #pragma unroll
        for (int i = 0; i < 4; i++)
            *(float4*)(g_P + base + i * 1024) = z;
    }
}

/* ---- warp-MMA GEMM (fp16), single-sync pipeline; mode0 fuses softmax*v ---- */
__global__ void __launch_bounds__(256, 2) k_mma(int mode, float* __restrict__ outp,
                                                const float* __restrict__ bo,
                                                const float* __restrict__ bk,
                                                const float* __restrict__ bv,
                                                const int* __restrict__ mask) {
    extern __shared__ __align__(16) char smc[];
    __shared__ float bks[64], bvs[64];
    const __half* Ap = mode ? g_loads : g_xs;
    const __half* Bp = mode ? g_wo : g_wkv;
    const int tid = threadIdx.x;
    const int rowBase = blockIdx.x * 128, colBase = blockIdx.y * 128;
    uint32_t sb = smem_u32(smc);

    if (mode == 0) {
        if (tid < 64)            bks[tid]      = bk[blockIdx.y * 64 + tid];
        else if (tid < 128)      bvs[tid - 64] = bv[blockIdx.y * 64 + tid - 64];
    }

    const int lr = tid >> 1, lsg = (tid & 1) * 4;
    const __half* gA = Ap + (size_t)(rowBase + lr) * TKE + lsg * 8;
    const __half* gB = Bp + (size_t)(colBase + lr) * TKE + lsg * 8;
    uint32_t sw[4];
    #pragma unroll
    for (int s = 0; s < 4; s++) {
        uint32_t o = lr * 128 + (lsg + s) * 16;
        sw[s] = o ^ ((o >> 3) & 0x70);
    }
    #define LOADC(c) do {                                                         \
        uint32_t stA = sb + ((c) % 3) * 32768, stB = stA + 16384;                 \
        const __half* pa = gA + (size_t)(c) * 64;                                 \
        const __half* pb = gB + (size_t)(c) * 64;                                 \
        cpa16(stA + sw[0], pa);      cpa16(stB + sw[0], pb);                      \
        cpa16(stA + sw[1], pa + 8);  cpa16(stB + sw[1], pb + 8);                  \
        cpa16(stA + sw[2], pa + 16); cpa16(stB + sw[2], pb + 16);                 \
        cpa16(stA + sw[3], pa + 24); cpa16(stB + sw[3], pb + 24);                 \
        asm volatile("cp.async.commit_group;" ::: "memory"); } while (0)

    const int w = tid >> 5, lane = tid & 31;
    const int wm = w & 1, wn = w >> 1;
    const int arow = wm * 64 + ((lane >> 3) & 1) * 8 + (lane & 7);
    const uint32_t akh = (lane >> 4) * 16;
    const uint32_t aSwz = (arow & 7) * 16;
    uint32_t aOff[4];
    #pragma unroll
    for (int mt = 0; mt < 4; mt++) aOff[mt] = (arow + mt * 16) * 128;
    const int bn = wn * 32 + ((lane >> 4) & 1) * 8 + (lane & 7);
    const uint32_t bkh = ((lane >> 3) & 1) * 16;
    const uint32_t bSwz = (bn & 7) * 16;
    uint32_t bOff[2];
    bOff[0] = bn * 128; bOff[1] = (bn + 16) * 128;

    float acc[4][4][4];
    #pragma unroll
    for (int i = 0; i < 4; i++)
        #pragma unroll
        for (int j = 0; j < 4; j++)
            #pragma unroll
            for (int q = 0; q < 4; q++) acc[i][j][q] = 0.0f;

    uint4 Af[2][4]; uint4 Bf[2][2];
    #define LDFRAG(buf, stA, stB, ksv) do {                                       \
        uint32_t ka = ((ksv) * 32 + akh) ^ aSwz;                                  \
        uint32_t kb = ((ksv) * 32 + bkh) ^ bSwz;                                  \
        Af[buf][0] = ldsm4((stA) + aOff[0] + ka);                                 \
        Af[buf][1] = ldsm4((stA) + aOff[1] + ka);                                 \
        Af[buf][2] = ldsm4((stA) + aOff[2] + ka);                                 \
        Af[buf][3] = ldsm4((stA) + aOff[3] + ka);                                 \
        Bf[buf][0] = ldsm4((stB) + bOff[0] + kb);                                 \
        Bf[buf][1] = ldsm4((stB) + bOff[1] + kb); } while (0)

    /* single-sync pipeline: prefetch distance 2, one barrier per chunk */
    LOADC(0); LOADC(1);
    for (int j = 0; j < NCH; j++) {
        if (j < NCH - 1) asm volatile("cp.async.wait_group 1;" ::: "memory");
        else             asm volatile("cp.async.wait_group 0;" ::: "memory");
        __syncthreads();
        uint32_t stA = sb + (j % 3) * 32768, stB = stA + 16384;
        if (j + 2 < NCH) LOADC(j + 2);   /* writes stage (j-1)%3: consumed last iter */
        LDFRAG(0, stA, stB, 0);
        #pragma unroll
        for (int ks = 0; ks < 4; ks++) {
            if (ks < 3) LDFRAG((ks + 1) & 1, stA, stB, ks + 1);
            const int cb = ks & 1;
            uint32_t bb[4][2] = {{Bf[cb][0].x, Bf[cb][0].y}, {Bf[cb][0].z, Bf[cb][0].w},
                                 {Bf[cb][1].x, Bf[cb][1].y}, {Bf[cb][1].z, Bf[cb][1].w}};
            #pragma unroll
            for (int mt = 0; mt < 4; mt++)
                #pragma unroll
                for (int nt = 0; nt < 4; nt++)
                    mma16816(acc[mt][nt], Af[cb][mt], bb[nt][0], bb[nt][1]);
        }
    }
    #undef LOADC
    #undef LDFRAG

    if (mode == 1) {
        const int crow0 = rowBase + wm * 64 + (lane >> 2);
        const int ccol0 = colBase + wn * 32 + (lane & 3) * 2;
        #pragma unroll
        for (int mt = 0; mt < 4; mt++) {
            #pragma unroll
            for (int nt = 0; nt < 4; nt++) {
                int row = crow0 + mt * 16, col = ccol0 + nt * 8;
                float b0 = bo[col], b1 = bo[col + 1];
                float2 v0 = make_float2(acc[mt][nt][0] + b0, acc[mt][nt][1] + b1);
                float2 v1 = make_float2(acc[mt][nt][2] + b0, acc[mt][nt][3] + b1);
                *(float2*)(outp + (size_t)row * 1024 + col) = v0;
                *(float2*)(outp + (size_t)(row + 8) * 1024 + col) = v1;
            }
        }
        return;
    }

    /* mode 0: stage scores to smem, per-row softmax(k)*v -> g_kv */
    __syncthreads();   /* all warps done with smem stages before reuse as Cs */
    float* Cs = (float*)smc;                  /* stride 129: conflict-free */
    const int lrow0 = wm * 64 + (lane >> 2);
    const int lcol0 = wn * 32 + (lane & 3) * 2;
    #pragma unroll
    for (int mt = 0; mt < 4; mt++) {
        #pragma unroll
        for (int nt = 0; nt < 4; nt++) {
            int rr = lrow0 + mt * 16, cc = lcol0 + nt * 8;
            Cs[rr * 129 + cc]           = acc[mt][nt][0];
            Cs[rr * 129 + cc + 1]       = acc[mt][nt][1];
            Cs[(rr + 8) * 129 + cc]     = acc[mt][nt][2];
            Cs[(rr + 8) * 129 + cc + 1] = acc[mt][nt][3];
        }
    }
    __syncthreads();
    {
        const int r = tid >> 1, half = tid & 1;
        float m = (float)mask[rowBase + r];
        float* crow = Cs + r * 129 + half * 32;       /* k: crow[0..31], v: crow[64..95] */
        const float* bkh_ = bks + half * 32;
        const float* bvh_ = bvs + half * 32;
        float mx = -INFINITY;
        #pragma unroll 8
        for (int i = 0; i < 32; i++) {
            float kk = (crow[i] + bkh_[i]) * m;
            crow[i] = kk; mx = fmaxf(mx, kk);
        }
        mx = fmaxf(mx, __shfl_xor_sync(0xffffffffu, mx, 1));
        float sum = 0.0f;
        #pragma unroll 8
        for (int i = 0; i < 32; i++) {
            float e = expf(crow[i] - mx);
            crow[i] = e; sum += e;
        }
        sum += __shfl_xor_sync(0xffffffffu, sum, 1);
        float inv = 1.0f / sum;
        float* dst = g_kv + (size_t)(rowBase + r) * 1024 + blockIdx.y * 64 + half * 32;
        #pragma unroll 8
        for (int i = 0; i < 32; i++)
            dst[i] = crow[i] * inv * (crow[64 + i] + bvh_[i]);
    }
}

/* ---- stage A: P[b,h,jj,d] = sum_l F[l,jj]*kv[b,l,h,d]; 32-row subtiles ---- */
__global__ void __launch_bounds__(256) k_stageA() {
    const int bh = blockIdx.x, b = bh >> 4, h = bh & 15;
    const int lbase0 = blockIdx.y * 256;
    const int tid = threadIdx.x, tx = tid & 15, ty = tid >> 4;
    __shared__ __align__(16) float F[32][64];
    __shared__ __align__(16) float KV[32][64];
    float acc[4][4] = {};
    for (int sub = 0; sub < 8; sub++) {
        int lbase = lbase0 + sub * 32;
        #pragma unroll
        for (int p = 0; p < 2; p++) {
            int e = tid + p * 256;                 /* 512 float4 per tile */
            int row = e >> 4, c4 = (e & 15) * 4;
            *(float4*)&F[row][c4]  = *(const float4*)(g_F + (size_t)(lbase + row) * 64 + c4);
            *(float4*)&KV[row][c4] = *(const float4*)(g_kv + (size_t)(b * TT + lbase + row) * DIMM + h * 64 + c4);
        }
        __syncthreads();
        #pragma unroll
        for (int l = 0; l < 32; l++) {
            float4 f4 = *(const float4*)&F[l][ty * 4];
            float4 k4 = *(const float4*)&KV[l][tx * 4];
            float ff[4] = {f4.x, f4.y, f4.z, f4.w};
            float kk[4] = {k4.x, k4.y, k4.z, k4.w};
            #pragma unroll
            for (int i = 0; i < 4; i++)
                #pragma unroll
                for (int j = 0; j < 4; j++) acc[i][j] += ff[i] * kk[j];
        }
        __syncthreads();
    }
    float* Pp = g_P + (size_t)bh * 4096;
    #pragma unroll
    for (int i = 0; i < 4; i++)
        #pragma unroll
        for (int j = 0; j < 4; j++)
            atomicAdd(&Pp[(ty*4 + i) * 64 + tx*4 + j], acc[i][j]);
}

/* ---- stage B: loading = G . P -> fp16 A; cp.async double-buffered over heads ---- */
__global__ void __launch_bounds__(256) k_stageB() {
    extern __shared__ __align__(16) char smb[];
    const int base = blockIdx.x * 32;
    const int b = base / TT, t0 = base - b * TT;
    const int tid = threadIdx.x, tx = tid & 15, ty = tid >> 4;
    uint32_t sbP = smem_u32(smb);            /* 2 x 16384 */
    uint32_t sbG = sbP + 32768;              /* 2 x 8704 ([32][68] floats) */

    #define LOADH(h) do {                                                          \
        int buf = (h) & 1;                                                         \
        uint32_t pd = sbP + buf * 16384;                                           \
        const float* ps = g_P + (size_t)(b * HH + (h)) * 4096;                     \
        _Pragma("unroll")                                                          \
        for (int p = 0; p < 4; p++)                                                \
            cpa16(pd + (tid + p * 256) * 16, ps + (tid + p * 256) * 4);            \
        uint32_t gd = sbG + buf * 8704;                                            \
        _Pragma("unroll")                                                          \
        for (int p = 0; p < 2; p++) {                                              \
            int e = tid + p * 256;                                                 \
            int row = e >> 4, seg = e & 15;                                        \
            cpa16(gd + row * 272 + seg * 16,                                       \
                  g_G + (size_t)((t0 + row) * HH + (h)) * 64 + seg * 4);           \
        }                                                                          \
        asm volatile("cp.async.commit_group;" ::: "memory"); } while (0)

    LOADH(0);
    for (int h = 0; h < HH; h++) {
        if (h + 1 < HH) LOADH(h + 1);                   /* overlaps compute of h */
        if (h + 1 < HH) asm volatile("cp.async.wait_group 1;" ::: "memory");
        else            asm volatile("cp.async.wait_group 0;" ::: "memory");
        __syncthreads();
        const float* Ph = (const float*)(smb + ((h & 1) ? 16384 : 0));
        const float* Gs = (const float*)(smb + 32768 + (h & 1) * 8704);
        float acc[2][4] = {};
        #pragma unroll
        for (int jj = 0; jj < 64; jj++) {
            float g0 = Gs[(ty*2 + 0) * 68 + jj];
            float g1 = Gs[(ty*2 + 1) * 68 + jj];
            float4 p = *(const float4*)&Ph[jj * 64 + tx * 4];
            acc[0][0] += g0*p.x; acc[0][1] += g0*p.y; acc[0][2] += g0*p.z; acc[0][3] += g0*p.w;
            acc[1][0] += g1*p.x; acc[1][1] += g1*p.y; acc[1][2] += g1*p.z; acc[1][3] += g1*p.w;
        }
        #pragma unroll
        for (int i = 0; i < 2; i++) {
            int row = base + ty*2 + i;
            float4 o = make_float4(acc[i][0], acc[i][1], acc[i][2], acc[i][3]);
            store_h4(g_loads + (size_t)row * TKE + h * 64 + tx * 4, o);
        }
        __syncthreads();                                /* buffer h&1 free for h+2's prefetch */
    }
    #undef LOADH
}

extern "C" void kernel_launch(void* const* d_in, const int* in_sizes, int n_in,
                              void* d_out, int out_size) {
    const float* states = (const float*)d_in[0];
    const int*   mask   = (const int*)  d_in[1];
    const float* lnw    = (const float*)d_in[2];
    const float* angles = (const float*)d_in[3];
    const float* hdelta = (const float*)d_in[4];
    const float* Wk = (const float*)d_in[7];
    const float* bk = (const float*)d_in[8];
    const float* Wv = (const float*)d_in[9];
    const float* bv = (const float*)d_in[10];
    const float* Wo = (const float*)d_in[11];
    const float* bo = (const float*)d_in[12];
    float* out = (float*)d_out;

    cudaFuncSetAttribute(k_mma, cudaFuncAttributeMaxDynamicSharedMemorySize, GSMEM);
    cudaFuncSetAttribute(k_stageB, cudaFuncAttributeMaxDynamicSharedMemorySize, SMB);

    k_prep<<<9248, 256>>>(states, lnw, Wk, Wv, Wo, angles, hdelta);

    dim3 gkv(MM / 128, HH);
    k_mma<<<gkv, 256, GSMEM>>>(0, nullptr, nullptr, bk, bv, mask);

    dim3 ga(BB * HH, 8);
    k_stageA<<<ga, 256>>>();
    k_stageB<<<MM / 32, 256, SMB>>>();

    dim3 go(MM / 128, DIMM / 128);
    k_mma<<<go, 256, GSMEM>>>(1, out, bo, nullptr, nullptr, nullptr);
}

// round 13
// speedup vs baseline: 1.5053x; 1.5053x over previous
#include <cuda_runtime.h>
#include <cuda_fp16.h>
#include <math.h>
#include <stdint.h>

#define BB 2
#define TT 2048
#define DIMM 1024
#define HH 16
#define MM (BB*TT)
#define TKE 1024
#define NCH 16
#define EPSF 1.1920928955078125e-07f
#define GSMEM (3*32768)

__device__ __align__(256) __half g_xs[(size_t)MM * TKE];
__device__ __align__(256) __half g_wkv[(size_t)2048 * TKE];  /* head-interleaved [k_h|v_h] */
__device__ __align__(256) __half g_wo[(size_t)1024 * TKE];
__device__ __align__(256) __half g_loads[(size_t)MM * TKE];
__device__ __align__(256) float g_kv[(size_t)MM * DIMM];
__device__ __align__(256) float g_F[TT * 64];
__device__ __align__(256) float g_G[TT * HH * 64];
__device__ __align__(256) float g_P[BB * HH * 64 * 64];

__device__ __forceinline__ uint32_t smem_u32(const void* p) {
    uint32_t a;
    asm("{ .reg .u64 t; cvta.to.shared.u64 t, %1; cvt.u32.u64 %0, t; }" : "=r"(a) : "l"(p));
    return a;
}
__device__ __forceinline__ void cpa16(uint32_t d, const void* s) {
    asm volatile("cp.async.cg.shared.global [%0], [%1], 16;" :: "r"(d), "l"(s));
}
/* fp32 Cody-Waite 2pi reduction: P1 products exact (n has <=8 mantissa bits) */
__device__ __forceinline__ void sincos_cw(float ang, float* s, float* c) {
    const float INV2PI = 0.15915494309189535f;
    const float P1 = 6.28125f;
    const float P2 = 1.9353071795864769e-3f;
    float n = rintf(ang * INV2PI);
    float r = fmaf(-n, P1, ang);
    r = fmaf(-n, P2, r);
    sincosf(r, s, c);
}
__device__ __forceinline__ void store_h4(__half* dst, float4 v) {
    __half2* d = (__half2*)dst;
    d[0] = __floats2half2_rn(v.x, v.y);
    d[1] = __floats2half2_rn(v.z, v.w);
}
__device__ __forceinline__ uint4 ldsm4(uint32_t a) {
    uint4 r;
    asm volatile("ldmatrix.sync.aligned.m8n8.x4.shared.b16 {%0,%1,%2,%3}, [%4];"
                 : "=r"(r.x), "=r"(r.y), "=r"(r.z), "=r"(r.w) : "r"(a));
    return r;
}
__device__ __forceinline__ void mma16816(float* c, uint4 a, uint32_t b0, uint32_t b1) {
    asm volatile("mma.sync.aligned.m16n8k16.row.col.f32.f16.f16.f32 "
                 "{%0,%1,%2,%3}, {%4,%5,%6,%7}, {%8,%9}, {%0,%1,%2,%3};"
                 : "+f"(c[0]), "+f"(c[1]), "+f"(c[2]), "+f"(c[3])
                 : "r"(a.x), "r"(a.y), "r"(a.z), "r"(a.w), "r"(b0), "r"(b1));
}

/* ---- weight conversion -> fp16; KV rows head-interleaved ---- */
__global__ void __launch_bounds__(256) k_convw(const float* __restrict__ Wk,
                                               const float* __restrict__ Wv,
                                               const float* __restrict__ Wo) {
    int row = blockIdx.x, tid = threadIdx.x;
    const float* src; __half* dst;
    if (row < 2048) {
        int h = row >> 7, c = row & 127;
        src = (c < 64) ? Wk + (size_t)(h * 64 + c) * 1024
                       : Wv + (size_t)(h * 64 + c - 64) * 1024;
        dst = g_wkv + (size_t)row * TKE;
    } else {
        src = Wo + (size_t)(row - 2048) * 1024;
        dst = g_wo + (size_t)(row - 2048) * TKE;
    }
    float4 v = ((const float4*)src)[tid];
    store_h4(dst + tid * 4, v);
}

/* ---- trig tables ---- */
__global__ void __launch_bounds__(256) k_trig(const float* __restrict__ angles,
                                              const float* __restrict__ hdelta) {
    int t = blockIdx.x, tid = threadIdx.x;
    __shared__ float w[32], hd[16];
    if (tid < 32) w[tid] = angles[tid];
    if (tid >= 32 && tid < 48) hd[tid - 32] = hdelta[tid - 32];
    __syncthreads();
    if (tid < 32) {
        float s, c; sincos_cw((float)t * w[tid], &s, &c);
        g_F[t * 64 + tid] = c; g_F[t * 64 + 32 + tid] = s;
    }
    for (int e = tid; e < 512; e += 256) {
        int h = e >> 5, j = e & 31;
        float s, c; sincos_cw(((float)t + hd[h]) * w[j], &s, &c);
        g_G[(size_t)(t * HH + h) * 64 + j]      = c * 0.03125f;
        g_G[(size_t)(t * HH + h) * 64 + 32 + j] = s * 0.03125f;
    }
}

/* ---- RMSNorm -> fp16 A ---- */
__global__ void __launch_bounds__(256) k_rmsnorm(const float* __restrict__ states,
                                                 const float* __restrict__ lnw) {
    int row = blockIdx.x, tid = threadIdx.x;
    float4 v = ((const float4*)(states + (size_t)row * DIMM))[tid];
    float ss = v.x*v.x + v.y*v.y + v.z*v.z + v.w*v.w;
    #pragma unroll
    for (int o = 16; o > 0; o >>= 1) ss += __shfl_xor_sync(0xffffffffu, ss, o);
    __shared__ float wsum[8];
    if ((tid & 31) == 0) wsum[tid >> 5] = ss;
    __syncthreads();
    if (tid < 8) {
        float s2 = wsum[tid];
        #pragma unroll
        for (int o = 4; o > 0; o >>= 1) s2 += __shfl_xor_sync(0xffu, s2, o);
        if (tid == 0) wsum[0] = s2;
    }
    __syncthreads();
    float sc = rsqrtf(wsum[0] * (1.0f / DIMM) + EPSF);
    float4 w = ((const float4*)lnw)[tid];
    float4 o = make_float4(v.x*sc*w.x, v.y*sc*w.y, v.z*sc*w.z, v.w*sc*w.w);
    store_h4(g_xs + (size_t)row * TKE + tid * 4, o);
}

/* ---- warp-MMA GEMM (fp16), single-sync pipeline; mode0 fuses softmax*v ---- */
__global__ void __launch_bounds__(256, 2) k_mma(int mode, float* __restrict__ outp,
                                                const float* __restrict__ bo,
                                                const float* __restrict__ bk,
                                                const float* __restrict__ bv,
                                                const int* __restrict__ mask) {
    extern __shared__ __align__(16) char smc[];
    __shared__ float bks[64], bvs[64];
    const __half* Ap = mode ? g_loads : g_xs;
    const __half* Bp = mode ? g_wo : g_wkv;
    const int tid = threadIdx.x;
    const int rowBase = blockIdx.x * 128, colBase = blockIdx.y * 128;
    uint32_t sb = smem_u32(smc);

    if (mode == 0) {
        if (tid < 64)            bks[tid]      = bk[blockIdx.y * 64 + tid];
        else if (tid < 128)      bvs[tid - 64] = bv[blockIdx.y * 64 + tid - 64];
    }

    const int lr = tid >> 1, lsg = (tid & 1) * 4;
    const __half* gA = Ap + (size_t)(rowBase + lr) * TKE + lsg * 8;
    const __half* gB = Bp + (size_t)(colBase + lr) * TKE + lsg * 8;
    uint32_t sw[4];
    #pragma unroll
    for (int s = 0; s < 4; s++) {
        uint32_t o = lr * 128 + (lsg + s) * 16;
        sw[s] = o ^ ((o >> 3) & 0x70);
    }
    #define LOADC(c) do {                                                         \
        uint32_t stA = sb + ((c) % 3) * 32768, stB = stA + 16384;                 \
        const __half* pa = gA + (size_t)(c) * 64;                                 \
        const __half* pb = gB + (size_t)(c) * 64;                                 \
        cpa16(stA + sw[0], pa);      cpa16(stB + sw[0], pb);                      \
        cpa16(stA + sw[1], pa + 8);  cpa16(stB + sw[1], pb + 8);                  \
        cpa16(stA + sw[2], pa + 16); cpa16(stB + sw[2], pb + 16);                 \
        cpa16(stA + sw[3], pa + 24); cpa16(stB + sw[3], pb + 24);                 \
        asm volatile("cp.async.commit_group;" ::: "memory"); } while (0)

    const int w = tid >> 5, lane = tid & 31;
    const int wm = w & 1, wn = w >> 1;
    const int arow = wm * 64 + ((lane >> 3) & 1) * 8 + (lane & 7);
    const uint32_t akh = (lane >> 4) * 16;
    const uint32_t aSwz = (arow & 7) * 16;
    uint32_t aOff[4];
    #pragma unroll
    for (int mt = 0; mt < 4; mt++) aOff[mt] = (arow + mt * 16) * 128;
    const int bn = wn * 32 + ((lane >> 4) & 1) * 8 + (lane & 7);
    const uint32_t bkh = ((lane >> 3) & 1) * 16;
    const uint32_t bSwz = (bn & 7) * 16;
    uint32_t bOff[2];
    bOff[0] = bn * 128; bOff[1] = (bn + 16) * 128;

    float acc[4][4][4];
    #pragma unroll
    for (int i = 0; i < 4; i++)
        #pragma unroll
        for (int j = 0; j < 4; j++)
            #pragma unroll
            for (int q = 0; q < 4; q++) acc[i][j][q] = 0.0f;

    uint4 Af[2][4]; uint4 Bf[2][2];
    #define LDFRAG(buf, stA, stB, ksv) do {                                       \
        uint32_t ka = ((ksv) * 32 + akh) ^ aSwz;                                  \
        uint32_t kb = ((ksv) * 32 + bkh) ^ bSwz;                                  \
        Af[buf][0] = ldsm4((stA) + aOff[0] + ka);                                 \
        Af[buf][1] = ldsm4((stA) + aOff[1] + ka);                                 \
        Af[buf][2] = ldsm4((stA) + aOff[2] + ka);                                 \
        Af[buf][3] = ldsm4((stA) + aOff[3] + ka);                                 \
        Bf[buf][0] = ldsm4((stB) + bOff[0] + kb);                                 \
        Bf[buf][1] = ldsm4((stB) + bOff[1] + kb); } while (0)

    /* single-sync pipeline: prefetch distance 2, one barrier per chunk */
    LOADC(0); LOADC(1);
    for (int j = 0; j < NCH; j++) {
        if (j < NCH - 1) asm volatile("cp.async.wait_group 1;" ::: "memory");
        else             asm volatile("cp.async.wait_group 0;" ::: "memory");
        __syncthreads();
        uint32_t stA = sb + (j % 3) * 32768, stB = stA + 16384;
        if (j + 2 < NCH) LOADC(j + 2);   /* writes stage (j-1)%3: consumed last iter */
        LDFRAG(0, stA, stB, 0);
        #pragma unroll
        for (int ks = 0; ks < 4; ks++) {
            if (ks < 3) LDFRAG((ks + 1) & 1, stA, stB, ks + 1);
            const int cb = ks & 1;
            uint32_t bb[4][2] = {{Bf[cb][0].x, Bf[cb][0].y}, {Bf[cb][0].z, Bf[cb][0].w},
                                 {Bf[cb][1].x, Bf[cb][1].y}, {Bf[cb][1].z, Bf[cb][1].w}};
            #pragma unroll
            for (int mt = 0; mt < 4; mt++)
                #pragma unroll
                for (int nt = 0; nt < 4; nt++)
                    mma16816(acc[mt][nt], Af[cb][mt], bb[nt][0], bb[nt][1]);
        }
    }
    #undef LOADC
    #undef LDFRAG

    if (mode == 1) {
        const int crow0 = rowBase + wm * 64 + (lane >> 2);
        const int ccol0 = colBase + wn * 32 + (lane & 3) * 2;
        #pragma unroll
        for (int mt = 0; mt < 4; mt++) {
            #pragma unroll
            for (int nt = 0; nt < 4; nt++) {
                int row = crow0 + mt * 16, col = ccol0 + nt * 8;
                float b0 = bo[col], b1 = bo[col + 1];
                float2 v0 = make_float2(acc[mt][nt][0] + b0, acc[mt][nt][1] + b1);
                float2 v1 = make_float2(acc[mt][nt][2] + b0, acc[mt][nt][3] + b1);
                *(float2*)(outp + (size_t)row * 1024 + col) = v0;
                *(float2*)(outp + (size_t)(row + 8) * 1024 + col) = v1;
            }
        }
        return;
    }

    /* mode 0: stage scores to smem, per-row softmax(k)*v -> g_kv */
    __syncthreads();   /* all warps done with smem stages before reuse as Cs */
    float* Cs = (float*)smc;                  /* stride 129: conflict-free */
    const int lrow0 = wm * 64 + (lane >> 2);
    const int lcol0 = wn * 32 + (lane & 3) * 2;
    #pragma unroll
    for (int mt = 0; mt < 4; mt++) {
        #pragma unroll
        for (int nt = 0; nt < 4; nt++) {
            int rr = lrow0 + mt * 16, cc = lcol0 + nt * 8;
            Cs[rr * 129 + cc]           = acc[mt][nt][0];
            Cs[rr * 129 + cc + 1]       = acc[mt][nt][1];
            Cs[(rr + 8) * 129 + cc]     = acc[mt][nt][2];
            Cs[(rr + 8) * 129 + cc + 1] = acc[mt][nt][3];
        }
    }
    __syncthreads();
    {
        const int r = tid >> 1, half = tid & 1;
        float m = (float)mask[rowBase + r];
        float* crow = Cs + r * 129 + half * 32;       /* k: crow[0..31], v: crow[64..95] */
        const float* bkh_ = bks + half * 32;
        const float* bvh_ = bvs + half * 32;
        float mx = -INFINITY;
        #pragma unroll 8
        for (int i = 0; i < 32; i++) {
            float kk = (crow[i] + bkh_[i]) * m;
            crow[i] = kk; mx = fmaxf(mx, kk);
        }
        mx = fmaxf(mx, __shfl_xor_sync(0xffffffffu, mx, 1));
        float sum = 0.0f;
        #pragma unroll 8
        for (int i = 0; i < 32; i++) {
            float e = expf(crow[i] - mx);
            crow[i] = e; sum += e;
        }
        sum += __shfl_xor_sync(0xffffffffu, sum, 1);
        float inv = 1.0f / sum;
        float* dst = g_kv + (size_t)(rowBase + r) * 1024 + blockIdx.y * 64 + half * 32;
        #pragma unroll 8
        for (int i = 0; i < 32; i++)
            dst[i] = crow[i] * inv * (crow[64 + i] + bvh_[i]);
    }
}

__global__ void k_zeroP() {
    int i = blockIdx.x * blockDim.x + threadIdx.x;
    if (i < BB * HH * 64 * 64) g_P[i] = 0.0f;
}

/* ---- stage A: P[b,h,jj,d] = sum_l F[l,jj]*kv[b,l,h,d] ---- */
__global__ void __launch_bounds__(256) k_stageA() {
    const int bh = blockIdx.x, b = bh >> 4, h = bh & 15;
    const int lbase0 = blockIdx.y * 256;
    const int tid = threadIdx.x, tx = tid & 15, ty = tid >> 4;
    __shared__ __align__(16) float F[16][64];
    __shared__ __align__(16) float KV[16][64];
    float acc[4][4] = {};
    for (int sub = 0; sub < 16; sub++) {
        int lbase = lbase0 + sub * 16;
        *(float4*)&F[ty][tx*4]  = *(const float4*)(g_F + (size_t)(lbase + ty) * 64 + tx * 4);
        *(float4*)&KV[ty][tx*4] = *(const float4*)(g_kv + (size_t)(b * TT + lbase + ty) * DIMM + h * 64 + tx * 4);
        __syncthreads();
        #pragma unroll
        for (int l = 0; l < 16; l++) {
            float4 f4 = *(const float4*)&F[l][ty * 4];
            float4 k4 = *(const float4*)&KV[l][tx * 4];
            float ff[4] = {f4.x, f4.y, f4.z, f4.w};
            float kk[4] = {k4.x, k4.y, k4.z, k4.w};
            #pragma unroll
            for (int i = 0; i < 4; i++)
                #pragma unroll
                for (int j = 0; j < 4; j++) acc[i][j] += ff[i] * kk[j];
        }
        __syncthreads();
    }
    float* Pp = g_P + (size_t)bh * 4096;
    #pragma unroll
    for (int i = 0; i < 4; i++)
        #pragma unroll
        for (int j = 0; j < 4; j++)
            atomicAdd(&Pp[(ty*4 + i) * 64 + tx*4 + j], acc[i][j]);
}

/* ---- stage B: loading = G . P -> fp16 A; one block per (row-block, head) ---- */
__global__ void __launch_bounds__(256) k_stageB() {
    const int base = blockIdx.x * 32;
    const int h = blockIdx.y;
    const int b = base / TT, t0 = base - b * TT;
    const int tid = threadIdx.x, tx = tid & 15, ty = tid >> 4;
    __shared__ __align__(16) float Ph[64][64];
    __shared__ __align__(16) float Gs[32][68];
    /* load P tile: 1024 float4 */
    {
        const float4* Psrc = (const float4*)(g_P + (size_t)(b * HH + h) * 4096);
        float4* Pd = (float4*)Ph;
        #pragma unroll
        for (int p = 0; p < 4; p++) Pd[tid + p * 256] = Psrc[tid + p * 256];
    }
    /* load G tile: 32 rows x 16 float4 */
    #pragma unroll
    for (int p = 0; p < 2; p++) {
        int e = tid + p * 256;
        int row = e >> 4, c4 = (e & 15) * 4;
        *(float4*)&Gs[row][c4] = *(const float4*)(g_G + (size_t)((t0 + row) * HH + h) * 64 + c4);
    }
    __syncthreads();
    float acc[2][4] = {};
    #pragma unroll
    for (int jj = 0; jj < 64; jj++) {
        float g0 = Gs[ty*2 + 0][jj];
        float g1 = Gs[ty*2 + 1][jj];
        float4 p = *(const float4*)&Ph[jj][tx * 4];
        acc[0][0] += g0*p.x; acc[0][1] += g0*p.y; acc[0][2] += g0*p.z; acc[0][3] += g0*p.w;
        acc[1][0] += g1*p.x; acc[1][1] += g1*p.y; acc[1][2] += g1*p.z; acc[1][3] += g1*p.w;
    }
    #pragma unroll
    for (int i = 0; i < 2; i++) {
        int row = base + ty*2 + i;
        float4 o = make_float4(acc[i][0], acc[i][1], acc[i][2], acc[i][3]);
        store_h4(g_loads + (size_t)row * TKE + h * 64 + tx * 4, o);
    }
}

extern "C" void kernel_launch(void* const* d_in, const int* in_sizes, int n_in,
                              void* d_out, int out_size) {
    const float* states = (const float*)d_in[0];
    const int*   mask   = (const int*)  d_in[1];
    const float* lnw    = (const float*)d_in[2];
    const float* angles = (const float*)d_in[3];
    const float* hdelta = (const float*)d_in[4];
    const float* Wk = (const float*)d_in[7];
    const float* bk = (const float*)d_in[8];
    const float* Wv = (const float*)d_in[9];
    const float* bv = (const float*)d_in[10];
    const float* Wo = (const float*)d_in[11];
    const float* bo = (const float*)d_in[12];
    float* out = (float*)d_out;

    cudaFuncSetAttribute(k_mma, cudaFuncAttributeMaxDynamicSharedMemorySize, GSMEM);

    k_convw<<<3072, 256>>>(Wk, Wv, Wo);
    k_trig<<<TT, 256>>>(angles, hdelta);
    k_rmsnorm<<<MM, 256>>>(states, lnw);

    dim3 gkv(MM / 128, HH);
    k_mma<<<gkv, 256, GSMEM>>>(0, nullptr, nullptr, bk, bv, mask);

    k_zeroP<<<(BB * HH * 64 * 64) / 256, 256>>>();
    dim3 ga(BB * HH, 8);
    k_stageA<<<ga, 256>>>();
    dim3 gb(MM / 32, HH);
    k_stageB<<<gb, 256>>>();

    dim3 go(MM / 128, DIMM / 128);
    k_mma<<<go, 256, GSMEM>>>(1, out, bo, nullptr, nullptr, nullptr);
}

// round 14
// speedup vs baseline: 1.5533x; 1.0319x over previous
#include <cuda_runtime.h>
#include <cuda_fp16.h>
#include <math.h>
#include <stdint.h>

#define BB 2
#define TT 2048
#define DIMM 1024
#define HH 16
#define MM (BB*TT)
#define TKE 1024
#define NCH 16
#define EPSF 1.1920928955078125e-07f
#define GSMEM (3*32768)

__device__ __align__(256) __half g_xs[(size_t)MM * TKE];
__device__ __align__(256) __half g_wkv[(size_t)2048 * TKE];  /* head-interleaved [k_h|v_h] */
__device__ __align__(256) __half g_wo[(size_t)1024 * TKE];
__device__ __align__(256) __half g_loads[(size_t)MM * TKE];
__device__ __align__(256) float g_kv[(size_t)MM * DIMM];
__device__ __align__(256) float g_F[TT * 64];
__device__ __align__(256) float g_G[TT * HH * 64];
__device__ __align__(256) float g_P[BB * HH * 64 * 64];

__device__ __forceinline__ uint32_t smem_u32(const void* p) {
    uint32_t a;
    asm("{ .reg .u64 t; cvta.to.shared.u64 t, %1; cvt.u32.u64 %0, t; }" : "=r"(a) : "l"(p));
    return a;
}
__device__ __forceinline__ void cpa16(uint32_t d, const void* s) {
    asm volatile("cp.async.cg.shared.global [%0], [%1], 16;" :: "r"(d), "l"(s));
}
/* fp32 Cody-Waite 2pi reduction: P1 products exact (n has <=8 mantissa bits) */
__device__ __forceinline__ void sincos_cw(float ang, float* s, float* c) {
    const float INV2PI = 0.15915494309189535f;
    const float P1 = 6.28125f;
    const float P2 = 1.9353071795864769e-3f;
    float n = rintf(ang * INV2PI);
    float r = fmaf(-n, P1, ang);
    r = fmaf(-n, P2, r);
    sincosf(r, s, c);
}
__device__ __forceinline__ void store_h4(__half* dst, float4 v) {
    __half2* d = (__half2*)dst;
    d[0] = __floats2half2_rn(v.x, v.y);
    d[1] = __floats2half2_rn(v.z, v.w);
}
__device__ __forceinline__ uint4 ldsm4(uint32_t a) {
    uint4 r;
    asm volatile("ldmatrix.sync.aligned.m8n8.x4.shared.b16 {%0,%1,%2,%3}, [%4];"
                 : "=r"(r.x), "=r"(r.y), "=r"(r.z), "=r"(r.w) : "r"(a));
    return r;
}
__device__ __forceinline__ void mma16816(float* c, uint4 a, uint32_t b0, uint32_t b1) {
    asm volatile("mma.sync.aligned.m16n8k16.row.col.f32.f16.f16.f32 "
                 "{%0,%1,%2,%3}, {%4,%5,%6,%7}, {%8,%9}, {%0,%1,%2,%3};"
                 : "+f"(c[0]), "+f"(c[1]), "+f"(c[2]), "+f"(c[3])
                 : "r"(a.x), "r"(a.y), "r"(a.z), "r"(a.w), "r"(b0), "r"(b1));
}

/* ---- fused prep: convw (0..3071) | trig (3072..5119) | rmsnorm (5120..9215) | zeroP (9216..9247) ---- */
__global__ void __launch_bounds__(256) k_prep(const float* __restrict__ states,
                                              const float* __restrict__ lnw,
                                              const float* __restrict__ Wk,
                                              const float* __restrict__ Wv,
                                              const float* __restrict__ Wo,
                                              const float* __restrict__ angles,
                                              const float* __restrict__ hdelta) {
    const int bid = blockIdx.x, tid = threadIdx.x;
    if (bid < 3072) {                                   /* weight conversion -> fp16 */
        int row = bid;
        const float* src; __half* dst;
        if (row < 2048) {
            int h = row >> 7, c = row & 127;
            src = (c < 64) ? Wk + (size_t)(h * 64 + c) * 1024
                           : Wv + (size_t)(h * 64 + c - 64) * 1024;
            dst = g_wkv + (size_t)row * TKE;
        } else {
            src = Wo + (size_t)(row - 2048) * 1024;
            dst = g_wo + (size_t)(row - 2048) * TKE;
        }
        float4 v = ((const float4*)src)[tid];
        store_h4(dst + tid * 4, v);
    } else if (bid < 5120) {                            /* trig tables */
        int t = bid - 3072;
        __shared__ float w[32], hd[16];
        if (tid < 32) w[tid] = angles[tid];
        if (tid >= 32 && tid < 48) hd[tid - 32] = hdelta[tid - 32];
        __syncthreads();
        if (tid < 32) {
            float s, c; sincos_cw((float)t * w[tid], &s, &c);
            g_F[t * 64 + tid] = c; g_F[t * 64 + 32 + tid] = s;
        }
        for (int e = tid; e < 512; e += 256) {
            int h = e >> 5, j = e & 31;
            float s, c; sincos_cw(((float)t + hd[h]) * w[j], &s, &c);
            g_G[(size_t)(t * HH + h) * 64 + j]      = c * 0.03125f;
            g_G[(size_t)(t * HH + h) * 64 + 32 + j] = s * 0.03125f;
        }
    } else if (bid < 9216) {                            /* RMSNorm -> fp16 A */
        int row = bid - 5120;
        float4 v = ((const float4*)(states + (size_t)row * DIMM))[tid];
        float ss = v.x*v.x + v.y*v.y + v.z*v.z + v.w*v.w;
        #pragma unroll
        for (int o = 16; o > 0; o >>= 1) ss += __shfl_xor_sync(0xffffffffu, ss, o);
        __shared__ float wsum[8];
        if ((tid & 31) == 0) wsum[tid >> 5] = ss;
        __syncthreads();
        if (tid < 8) {
            float s2 = wsum[tid];
            #pragma unroll
            for (int o = 4; o > 0; o >>= 1) s2 += __shfl_xor_sync(0xffu, s2, o);
            if (tid == 0) wsum[0] = s2;
        }
        __syncthreads();
        float sc = rsqrtf(wsum[0] * (1.0f / DIMM) + EPSF);
        float4 w = ((const float4*)lnw)[tid];
        float4 o = make_float4(v.x*sc*w.x, v.y*sc*w.y, v.z*sc*w.z, v.w*sc*w.w);
        store_h4(g_xs + (size_t)row * TKE + tid * 4, o);
    } else {                                            /* zero g_P: 32 blocks x 4096 floats */
        int base = (bid - 9216) * 4096 + tid * 4;
        float4 z = make_float4(0.f, 0.f, 0.f, 0.f);
        #pragma unroll
        for (int i = 0; i < 4; i++)
            *(float4*)(g_P + base + i * 1024) = z;
    }
}

/* ---- warp-MMA GEMM (fp16), single-sync pipeline; mode0 fuses softmax*v ---- */
__global__ void __launch_bounds__(256, 2) k_mma(int mode, float* __restrict__ outp,
                                                const float* __restrict__ bo,
                                                const float* __restrict__ bk,
                                                const float* __restrict__ bv,
                                                const int* __restrict__ mask) {
    extern __shared__ __align__(16) char smc[];
    __shared__ float bks[64], bvs[64];
    const __half* Ap = mode ? g_loads : g_xs;
    const __half* Bp = mode ? g_wo : g_wkv;
    const int tid = threadIdx.x;
    const int rowBase = blockIdx.x * 128, colBase = blockIdx.y * 128;
    uint32_t sb = smem_u32(smc);

    if (mode == 0) {
        if (tid < 64)            bks[tid]      = bk[blockIdx.y * 64 + tid];
        else if (tid < 128)      bvs[tid - 64] = bv[blockIdx.y * 64 + tid - 64];
    }

    const int lr = tid >> 1, lsg = (tid & 1) * 4;
    const __half* gA = Ap + (size_t)(rowBase + lr) * TKE + lsg * 8;
    const __half* gB = Bp + (size_t)(colBase + lr) * TKE + lsg * 8;
    uint32_t sw[4];
    #pragma unroll
    for (int s = 0; s < 4; s++) {
        uint32_t o = lr * 128 + (lsg + s) * 16;
        sw[s] = o ^ ((o >> 3) & 0x70);
    }
    #define LOADC(c) do {                                                         \
        uint32_t stA = sb + ((c) % 3) * 32768, stB = stA + 16384;                 \
        const __half* pa = gA + (size_t)(c) * 64;                                 \
        const __half* pb = gB + (size_t)(c) * 64;                                 \
        cpa16(stA + sw[0], pa);      cpa16(stB + sw[0], pb);                      \
        cpa16(stA + sw[1], pa + 8);  cpa16(stB + sw[1], pb + 8);                  \
        cpa16(stA + sw[2], pa + 16); cpa16(stB + sw[2], pb + 16);                 \
        cpa16(stA + sw[3], pa + 24); cpa16(stB + sw[3], pb + 24);                 \
        asm volatile("cp.async.commit_group;" ::: "memory"); } while (0)

    const int w = tid >> 5, lane = tid & 31;
    const int wm = w & 1, wn = w >> 1;
    const int arow = wm * 64 + ((lane >> 3) & 1) * 8 + (lane & 7);
    const uint32_t akh = (lane >> 4) * 16;
    const uint32_t aSwz = (arow & 7) * 16;
    uint32_t aOff[4];
    #pragma unroll
    for (int mt = 0; mt < 4; mt++) aOff[mt] = (arow + mt * 16) * 128;
    const int bn = wn * 32 + ((lane >> 4) & 1) * 8 + (lane & 7);
    const uint32_t bkh = ((lane >> 3) & 1) * 16;
    const uint32_t bSwz = (bn & 7) * 16;
    uint32_t bOff[2];
    bOff[0] = bn * 128; bOff[1] = (bn + 16) * 128;

    float acc[4][4][4];
    #pragma unroll
    for (int i = 0; i < 4; i++)
        #pragma unroll
        for (int j = 0; j < 4; j++)
            #pragma unroll
            for (int q = 0; q < 4; q++) acc[i][j][q] = 0.0f;

    uint4 Af[2][4]; uint4 Bf[2][2];
    #define LDFRAG(buf, stA, stB, ksv) do {                                       \
        uint32_t ka = ((ksv) * 32 + akh) ^ aSwz;                                  \
        uint32_t kb = ((ksv) * 32 + bkh) ^ bSwz;                                  \
        Af[buf][0] = ldsm4((stA) + aOff[0] + ka);                                 \
        Af[buf][1] = ldsm4((stA) + aOff[1] + ka);                                 \
        Af[buf][2] = ldsm4((stA) + aOff[2] + ka);                                 \
        Af[buf][3] = ldsm4((stA) + aOff[3] + ka);                                 \
        Bf[buf][0] = ldsm4((stB) + bOff[0] + kb);                                 \
        Bf[buf][1] = ldsm4((stB) + bOff[1] + kb); } while (0)

    /* single-sync pipeline: prefetch distance 2, one barrier per chunk */
    LOADC(0); LOADC(1);
    for (int j = 0; j < NCH; j++) {
        if (j < NCH - 1) asm volatile("cp.async.wait_group 1;" ::: "memory");
        else             asm volatile("cp.async.wait_group 0;" ::: "memory");
        __syncthreads();
        uint32_t stA = sb + (j % 3) * 32768, stB = stA + 16384;
        if (j + 2 < NCH) LOADC(j + 2);   /* writes stage (j-1)%3: consumed last iter */
        LDFRAG(0, stA, stB, 0);
        #pragma unroll
        for (int ks = 0; ks < 4; ks++) {
            if (ks < 3) LDFRAG((ks + 1) & 1, stA, stB, ks + 1);
            const int cb = ks & 1;
            uint32_t bb[4][2] = {{Bf[cb][0].x, Bf[cb][0].y}, {Bf[cb][0].z, Bf[cb][0].w},
                                 {Bf[cb][1].x, Bf[cb][1].y}, {Bf[cb][1].z, Bf[cb][1].w}};
            #pragma unroll
            for (int mt = 0; mt < 4; mt++)
                #pragma unroll
                for (int nt = 0; nt < 4; nt++)
                    mma16816(acc[mt][nt], Af[cb][mt], bb[nt][0], bb[nt][1]);
        }
    }
    #undef LOADC
    #undef LDFRAG

    if (mode == 1) {
        const int crow0 = rowBase + wm * 64 + (lane >> 2);
        const int ccol0 = colBase + wn * 32 + (lane & 3) * 2;
        #pragma unroll
        for (int mt = 0; mt < 4; mt++) {
            #pragma unroll
            for (int nt = 0; nt < 4; nt++) {
                int row = crow0 + mt * 16, col = ccol0 + nt * 8;
                float b0 = bo[col], b1 = bo[col + 1];
                float2 v0 = make_float2(acc[mt][nt][0] + b0, acc[mt][nt][1] + b1);
                float2 v1 = make_float2(acc[mt][nt][2] + b0, acc[mt][nt][3] + b1);
                *(float2*)(outp + (size_t)row * 1024 + col) = v0;
                *(float2*)(outp + (size_t)(row + 8) * 1024 + col) = v1;
            }
        }
        return;
    }

    /* mode 0: stage scores to smem, per-row softmax(k)*v -> g_kv */
    __syncthreads();   /* all warps done with smem stages before reuse as Cs */
    float* Cs = (float*)smc;                  /* stride 129: conflict-free */
    const int lrow0 = wm * 64 + (lane >> 2);
    const int lcol0 = wn * 32 + (lane & 3) * 2;
    #pragma unroll
    for (int mt = 0; mt < 4; mt++) {
        #pragma unroll
        for (int nt = 0; nt < 4; nt++) {
            int rr = lrow0 + mt * 16, cc = lcol0 + nt * 8;
            Cs[rr * 129 + cc]           = acc[mt][nt][0];
            Cs[rr * 129 + cc + 1]       = acc[mt][nt][1];
            Cs[(rr + 8) * 129 + cc]     = acc[mt][nt][2];
            Cs[(rr + 8) * 129 + cc + 1] = acc[mt][nt][3];
        }
    }
    __syncthreads();
    {
        const int r = tid >> 1, half = tid & 1;
        float m = (float)mask[rowBase + r];
        float* crow = Cs + r * 129 + half * 32;       /* k: crow[0..31], v: crow[64..95] */
        const float* bkh_ = bks + half * 32;
        const float* bvh_ = bvs + half * 32;
        float mx = -INFINITY;
        #pragma unroll 8
        for (int i = 0; i < 32; i++) {
            float kk = (crow[i] + bkh_[i]) * m;
            crow[i] = kk; mx = fmaxf(mx, kk);
        }
        mx = fmaxf(mx, __shfl_xor_sync(0xffffffffu, mx, 1));
        float sum = 0.0f;
        #pragma unroll 8
        for (int i = 0; i < 32; i++) {
            float e = expf(crow[i] - mx);
            crow[i] = e; sum += e;
        }
        sum += __shfl_xor_sync(0xffffffffu, sum, 1);
        float inv = 1.0f / sum;
        float* dst = g_kv + (size_t)(rowBase + r) * 1024 + blockIdx.y * 64 + half * 32;
        #pragma unroll 8
        for (int i = 0; i < 32; i++)
            dst[i] = crow[i] * inv * (crow[64 + i] + bvh_[i]);
    }
}

/* ---- stage A: P[b,h,jj,d] = sum_l F[l,jj]*kv[b,l,h,d]; 16 splits x 128 l ---- */
__global__ void __launch_bounds__(256) k_stageA() {
    const int bh = blockIdx.x, b = bh >> 4, h = bh & 15;
    const int lbase0 = blockIdx.y * 128;
    const int tid = threadIdx.x, tx = tid & 15, ty = tid >> 4;
    __shared__ __align__(16) float F[16][64];
    __shared__ __align__(16) float KV[16][64];
    float acc[4][4] = {};
    for (int sub = 0; sub < 8; sub++) {
        int lbase = lbase0 + sub * 16;
        *(float4*)&F[ty][tx*4]  = *(const float4*)(g_F + (size_t)(lbase + ty) * 64 + tx * 4);
        *(float4*)&KV[ty][tx*4] = *(const float4*)(g_kv + (size_t)(b * TT + lbase + ty) * DIMM + h * 64 + tx * 4);
        __syncthreads();
        #pragma unroll
        for (int l = 0; l < 16; l++) {
            float4 f4 = *(const float4*)&F[l][ty * 4];
            float4 k4 = *(const float4*)&KV[l][tx * 4];
            float ff[4] = {f4.x, f4.y, f4.z, f4.w};
            float kk[4] = {k4.x, k4.y, k4.z, k4.w};
            #pragma unroll
            for (int i = 0; i < 4; i++)
                #pragma unroll
                for (int j = 0; j < 4; j++) acc[i][j] += ff[i] * kk[j];
        }
        __syncthreads();
    }
    float* Pp = g_P + (size_t)bh * 4096;
    #pragma unroll
    for (int i = 0; i < 4; i++)
        #pragma unroll
        for (int j = 0; j < 4; j++)
            atomicAdd(&Pp[(ty*4 + i) * 64 + tx*4 + j], acc[i][j]);
}

/* ---- stage B: loading = G . P -> fp16 A; one block per (row-block, head) ---- */
__global__ void __launch_bounds__(256) k_stageB() {
    const int base = blockIdx.x * 32;
    const int h = blockIdx.y;
    const int b = base / TT, t0 = base - b * TT;
    const int tid = threadIdx.x, tx = tid & 15, ty = tid >> 4;
    __shared__ __align__(16) float Ph[64][64];
    __shared__ __align__(16) float Gs[32][68];
    {
        const float4* Psrc = (const float4*)(g_P + (size_t)(b * HH + h) * 4096);
        float4* Pd = (float4*)Ph;
        #pragma unroll
        for (int p = 0; p < 4; p++) Pd[tid + p * 256] = Psrc[tid + p * 256];
    }
    #pragma unroll
    for (int p = 0; p < 2; p++) {
        int e = tid + p * 256;
        int row = e >> 4, c4 = (e & 15) * 4;
        *(float4*)&Gs[row][c4] = *(const float4*)(g_G + (size_t)((t0 + row) * HH + h) * 64 + c4);
    }
    __syncthreads();
    float acc[2][4] = {};
    #pragma unroll
    for (int jj = 0; jj < 64; jj++) {
        float g0 = Gs[ty*2 + 0][jj];
        float g1 = Gs[ty*2 + 1][jj];
        float4 p = *(const float4*)&Ph[jj][tx * 4];
        acc[0][0] += g0*p.x; acc[0][1] += g0*p.y; acc[0][2] += g0*p.z; acc[0][3] += g0*p.w;
        acc[1][0] += g1*p.x; acc[1][1] += g1*p.y; acc[1][2] += g1*p.z; acc[1][3] += g1*p.w;
    }
    #pragma unroll
    for (int i = 0; i < 2; i++) {
        int row = base + ty*2 + i;
        float4 o = make_float4(acc[i][0], acc[i][1], acc[i][2], acc[i][3]);
        store_h4(g_loads + (size_t)row * TKE + h * 64 + tx * 4, o);
    }
}

extern "C" void kernel_launch(void* const* d_in, const int* in_sizes, int n_in,
                              void* d_out, int out_size) {
    const float* states = (const float*)d_in[0];
    const int*   mask   = (const int*)  d_in[1];
    const float* lnw    = (const float*)d_in[2];
    const float* angles = (const float*)d_in[3];
    const float* hdelta = (const float*)d_in[4];
    const float* Wk = (const float*)d_in[7];
    const float* bk = (const float*)d_in[8];
    const float* Wv = (const float*)d_in[9];
    const float* bv = (const float*)d_in[10];
    const float* Wo = (const float*)d_in[11];
    const float* bo = (const float*)d_in[12];
    float* out = (float*)d_out;

    cudaFuncSetAttribute(k_mma, cudaFuncAttributeMaxDynamicSharedMemorySize, GSMEM);

    k_prep<<<9248, 256>>>(states, lnw, Wk, Wv, Wo, angles, hdelta);

    dim3 gkv(MM / 128, HH);
    k_mma<<<gkv, 256, GSMEM>>>(0, nullptr, nullptr, bk, bv, mask);

    dim3 ga(BB * HH, 16);
    k_stageA<<<ga, 256>>>();
    dim3 gb(MM / 32, HH);
    k_stageB<<<gb, 256>>>();

    dim3 go(MM / 128, DIMM / 128);
    k_mma<<<go, 256, GSMEM>>>(1, out, bo, nullptr, nullptr, nullptr);
}

// round 15
// speedup vs baseline: 1.6167x; 1.0409x over previous
#include <cuda_runtime.h>
#include <cuda_fp16.h>
#include <math.h>
#include <stdint.h>

#define BB 2
#define TT 2048
#define DIMM 1024
#define HH 16
#define MM (BB*TT)
#define TKE 1024
#define NCH 16
#define EPSF 1.1920928955078125e-07f
#define GSMEM (3*32768)

__device__ __align__(256) __half g_xs[(size_t)MM * TKE];
__device__ __align__(256) __half g_wkv[(size_t)2048 * TKE];  /* head-interleaved [k_h|v_h] */
__device__ __align__(256) __half g_wo[(size_t)1024 * TKE];
__device__ __align__(256) __half g_loads[(size_t)MM * TKE];
__device__ __align__(256) float g_kv[(size_t)MM * DIMM];
__device__ __align__(256) float g_F[TT * 64];
__device__ __align__(256) float g_G[TT * HH * 64];
__device__ __align__(256) float g_P[BB * HH * 64 * 64];

__device__ __forceinline__ uint32_t smem_u32(const void* p) {
    uint32_t a;
    asm("{ .reg .u64 t; cvta.to.shared.u64 t, %1; cvt.u32.u64 %0, t; }" : "=r"(a) : "l"(p));
    return a;
}
__device__ __forceinline__ void cpa16(uint32_t d, const void* s) {
    asm volatile("cp.async.cg.shared.global [%0], [%1], 16;" :: "r"(d), "l"(s));
}
/* fp32 Cody-Waite 2pi reduction: P1 products exact (n has <=8 mantissa bits) */
__device__ __forceinline__ void sincos_cw(float ang, float* s, float* c) {
    const float INV2PI = 0.15915494309189535f;
    const float P1 = 6.28125f;
    const float P2 = 1.9353071795864769e-3f;
    float n = rintf(ang * INV2PI);
    float r = fmaf(-n, P1, ang);
    r = fmaf(-n, P2, r);
    sincosf(r, s, c);
}
__device__ __forceinline__ void store_h4(__half* dst, float4 v) {
    __half2* d = (__half2*)dst;
    d[0] = __floats2half2_rn(v.x, v.y);
    d[1] = __floats2half2_rn(v.z, v.w);
}
__device__ __forceinline__ uint4 ldsm4(uint32_t a) {
    uint4 r;
    asm volatile("ldmatrix.sync.aligned.m8n8.x4.shared.b16 {%0,%1,%2,%3}, [%4];"
                 : "=r"(r.x), "=r"(r.y), "=r"(r.z), "=r"(r.w) : "r"(a));
    return r;
}
__device__ __forceinline__ void mma16816(float* c, uint4 a, uint32_t b0, uint32_t b1) {
    asm volatile("mma.sync.aligned.m16n8k16.row.col.f32.f16.f16.f32 "
                 "{%0,%1,%2,%3}, {%4,%5,%6,%7}, {%8,%9}, {%0,%1,%2,%3};"
                 : "+f"(c[0]), "+f"(c[1]), "+f"(c[2]), "+f"(c[3])
                 : "r"(a.x), "r"(a.y), "r"(a.z), "r"(a.w), "r"(b0), "r"(b1));
}

/* ---- fused prep: convw (0..3071) | trig (3072..5119) | rmsnorm (5120..9215) | zeroP (9216..9247) ---- */
__global__ void __launch_bounds__(256) k_prep(const float* __restrict__ states,
                                              const float* __restrict__ lnw,
                                              const float* __restrict__ Wk,
                                              const float* __restrict__ Wv,
                                              const float* __restrict__ Wo,
                                              const float* __restrict__ angles,
                                              const float* __restrict__ hdelta) {
    const int bid = blockIdx.x, tid = threadIdx.x;
    if (bid < 3072) {                                   /* weight conversion -> fp16 */
        int row = bid;
        const float* src; __half* dst;
        if (row < 2048) {
            int h = row >> 7, c = row & 127;
            src = (c < 64) ? Wk + (size_t)(h * 64 + c) * 1024
                           : Wv + (size_t)(h * 64 + c - 64) * 1024;
            dst = g_wkv + (size_t)row * TKE;
        } else {
            src = Wo + (size_t)(row - 2048) * 1024;
            dst = g_wo + (size_t)(row - 2048) * TKE;
        }
        float4 v = ((const float4*)src)[tid];
        store_h4(dst + tid * 4, v);
    } else if (bid < 5120) {                            /* trig tables */
        int t = bid - 3072;
        __shared__ float w[32], hd[16];
        if (tid < 32) w[tid] = angles[tid];
        if (tid >= 32 && tid < 48) hd[tid - 32] = hdelta[tid - 32];
        __syncthreads();
        if (tid < 32) {
            float s, c; sincos_cw((float)t * w[tid], &s, &c);
            g_F[t * 64 + tid] = c; g_F[t * 64 + 32 + tid] = s;
        }
        for (int e = tid; e < 512; e += 256) {
            int h = e >> 5, j = e & 31;
            float s, c; sincos_cw(((float)t + hd[h]) * w[j], &s, &c);
            g_G[(size_t)(t * HH + h) * 64 + j]      = c * 0.03125f;
            g_G[(size_t)(t * HH + h) * 64 + 32 + j] = s * 0.03125f;
        }
    } else if (bid < 9216) {                            /* RMSNorm -> fp16 A */
        int row = bid - 5120;
        float4 v = ((const float4*)(states + (size_t)row * DIMM))[tid];
        float ss = v.x*v.x + v.y*v.y + v.z*v.z + v.w*v.w;
        #pragma unroll
        for (int o = 16; o > 0; o >>= 1) ss += __shfl_xor_sync(0xffffffffu, ss, o);
        __shared__ float wsum[8];
        if ((tid & 31) == 0) wsum[tid >> 5] = ss;
        __syncthreads();
        if (tid < 8) {
            float s2 = wsum[tid];
            #pragma unroll
            for (int o = 4; o > 0; o >>= 1) s2 += __shfl_xor_sync(0xffu, s2, o);
            if (tid == 0) wsum[0] = s2;
        }
        __syncthreads();
        float sc = rsqrtf(wsum[0] * (1.0f / DIMM) + EPSF);
        float4 w = ((const float4*)lnw)[tid];
        float4 o = make_float4(v.x*sc*w.x, v.y*sc*w.y, v.z*sc*w.z, v.w*sc*w.w);
        store_h4(g_xs + (size_t)row * TKE + tid * 4, o);
    } else {                                            /* zero g_P: 32 blocks x 4096 floats */
        int base = (bid - 9216) * 4096 + tid * 4;
        float4 z = make_float4(0.f, 0.f, 0.f, 0.f);
        #pragma unroll
        for (int i = 0; i < 4; i++)
            *(float4*)(g_P + base + i * 1024) = z;
    }
}

/* ---- warp-MMA GEMM (fp16), single-sync pipeline; mode0 fuses softmax*v ---- */
__global__ void __launch_bounds__(256, 2) k_mma(int mode, float* __restrict__ outp,
                                                const float* __restrict__ bo,
                                                const float* __restrict__ bk,
                                                const float* __restrict__ bv,
                                                const int* __restrict__ mask) {
    extern __shared__ __align__(16) char smc[];
    __shared__ float bks[64], bvs[64];
    const __half* Ap = mode ? g_loads : g_xs;
    const __half* Bp = mode ? g_wo : g_wkv;
    const int tid = threadIdx.x;
    const int rowBase = blockIdx.x * 128, colBase = blockIdx.y * 128;
    uint32_t sb = smem_u32(smc);

    if (mode == 0) {
        if (tid < 64)            bks[tid]      = bk[blockIdx.y * 64 + tid];
        else if (tid < 128)      bvs[tid - 64] = bv[blockIdx.y * 64 + tid - 64];
    }

    const int lr = tid >> 1, lsg = (tid & 1) * 4;
    const __half* gA = Ap + (size_t)(rowBase + lr) * TKE + lsg * 8;
    const __half* gB = Bp + (size_t)(colBase + lr) * TKE + lsg * 8;
    uint32_t sw[4];
    #pragma unroll
    for (int s = 0; s < 4; s++) {
        uint32_t o = lr * 128 + (lsg + s) * 16;
        sw[s] = o ^ ((o >> 3) & 0x70);
    }
    #define LOADC(c) do {                                                         \
        uint32_t stA = sb + ((c) % 3) * 32768, stB = stA + 16384;                 \
        const __half* pa = gA + (size_t)(c) * 64;                                 \
        const __half* pb = gB + (size_t)(c) * 64;                                 \
        cpa16(stA + sw[0], pa);      cpa16(stB + sw[0], pb);                      \
        cpa16(stA + sw[1], pa + 8);  cpa16(stB + sw[1], pb + 8);                  \
        cpa16(stA + sw[2], pa + 16); cpa16(stB + sw[2], pb + 16);                 \
        cpa16(stA + sw[3], pa + 24); cpa16(stB + sw[3], pb + 24);                 \
        asm volatile("cp.async.commit_group;" ::: "memory"); } while (0)

    const int w = tid >> 5, lane = tid & 31;
    const int wm = w & 1, wn = w >> 1;
    const int arow = wm * 64 + ((lane >> 3) & 1) * 8 + (lane & 7);
    const uint32_t akh = (lane >> 4) * 16;
    const uint32_t aSwz = (arow & 7) * 16;
    uint32_t aOff[4];
    #pragma unroll
    for (int mt = 0; mt < 4; mt++) aOff[mt] = (arow + mt * 16) * 128;
    const int bn = wn * 32 + ((lane >> 4) & 1) * 8 + (lane & 7);
    const uint32_t bkh = ((lane >> 3) & 1) * 16;
    const uint32_t bSwz = (bn & 7) * 16;
    uint32_t bOff[2];
    bOff[0] = bn * 128; bOff[1] = (bn + 16) * 128;

    float acc[4][4][4];
    #pragma unroll
    for (int i = 0; i < 4; i++)
        #pragma unroll
        for (int j = 0; j < 4; j++)
            #pragma unroll
            for (int q = 0; q < 4; q++) acc[i][j][q] = 0.0f;

    uint4 Af[2][4]; uint4 Bf[2][2];
    #define LDFRAG(buf, stA, stB, ksv) do {                                       \
        uint32_t ka = ((ksv) * 32 + akh) ^ aSwz;                                  \
        uint32_t kb = ((ksv) * 32 + bkh) ^ bSwz;                                  \
        Af[buf][0] = ldsm4((stA) + aOff[0] + ka);                                 \
        Af[buf][1] = ldsm4((stA) + aOff[1] + ka);                                 \
        Af[buf][2] = ldsm4((stA) + aOff[2] + ka);                                 \
        Af[buf][3] = ldsm4((stA) + aOff[3] + ka);                                 \
        Bf[buf][0] = ldsm4((stB) + bOff[0] + kb);                                 \
        Bf[buf][1] = ldsm4((stB) + bOff[1] + kb); } while (0)

    /* single-sync pipeline: prefetch distance 2, one barrier per chunk */
    LOADC(0); LOADC(1);
    for (int j = 0; j < NCH; j++) {
        if (j < NCH - 1) asm volatile("cp.async.wait_group 1;" ::: "memory");
        else             asm volatile("cp.async.wait_group 0;" ::: "memory");
        __syncthreads();
        uint32_t stA = sb + (j % 3) * 32768, stB = stA + 16384;
        if (j + 2 < NCH) LOADC(j + 2);   /* writes stage (j-1)%3: consumed last iter */
        LDFRAG(0, stA, stB, 0);
        #pragma unroll
        for (int ks = 0; ks < 4; ks++) {
            if (ks < 3) LDFRAG((ks + 1) & 1, stA, stB, ks + 1);
            const int cb = ks & 1;
            uint32_t bb[4][2] = {{Bf[cb][0].x, Bf[cb][0].y}, {Bf[cb][0].z, Bf[cb][0].w},
                                 {Bf[cb][1].x, Bf[cb][1].y}, {Bf[cb][1].z, Bf[cb][1].w}};
            #pragma unroll
            for (int mt = 0; mt < 4; mt++)
                #pragma unroll
                for (int nt = 0; nt < 4; nt++)
                    mma16816(acc[mt][nt], Af[cb][mt], bb[nt][0], bb[nt][1]);
        }
    }
    #undef LOADC
    #undef LDFRAG

    if (mode == 1) {
        const int crow0 = rowBase + wm * 64 + (lane >> 2);
        const int ccol0 = colBase + wn * 32 + (lane & 3) * 2;
        #pragma unroll
        for (int mt = 0; mt < 4; mt++) {
            #pragma unroll
            for (int nt = 0; nt < 4; nt++) {
                int row = crow0 + mt * 16, col = ccol0 + nt * 8;
                float b0 = bo[col], b1 = bo[col + 1];
                float2 v0 = make_float2(acc[mt][nt][0] + b0, acc[mt][nt][1] + b1);
                float2 v1 = make_float2(acc[mt][nt][2] + b0, acc[mt][nt][3] + b1);
                *(float2*)(outp + (size_t)row * 1024 + col) = v0;
                *(float2*)(outp + (size_t)(row + 8) * 1024 + col) = v1;
            }
        }
        return;
    }

    /* mode 0: stage scores to smem, per-row softmax(k)*v -> g_kv */
    __syncthreads();   /* all warps done with smem stages before reuse as Cs */
    float* Cs = (float*)smc;                  /* stride 129: conflict-free */
    const int lrow0 = wm * 64 + (lane >> 2);
    const int lcol0 = wn * 32 + (lane & 3) * 2;
    #pragma unroll
    for (int mt = 0; mt < 4; mt++) {
        #pragma unroll
        for (int nt = 0; nt < 4; nt++) {
            int rr = lrow0 + mt * 16, cc = lcol0 + nt * 8;
            Cs[rr * 129 + cc]           = acc[mt][nt][0];
            Cs[rr * 129 + cc + 1]       = acc[mt][nt][1];
            Cs[(rr + 8) * 129 + cc]     = acc[mt][nt][2];
            Cs[(rr + 8) * 129 + cc + 1] = acc[mt][nt][3];
        }
    }
    __syncthreads();
    {
        const int r = tid >> 1, half = tid & 1;
        float m = (float)mask[rowBase + r];
        float* crow = Cs + r * 129 + half * 32;       /* k: crow[0..31], v: crow[64..95] */
        const float* bkh_ = bks + half * 32;
        const float* bvh_ = bvs + half * 32;
        float mx = -INFINITY;
        #pragma unroll 8
        for (int i = 0; i < 32; i++) {
            float kk = (crow[i] + bkh_[i]) * m;
            crow[i] = kk; mx = fmaxf(mx, kk);
        }
        mx = fmaxf(mx, __shfl_xor_sync(0xffffffffu, mx, 1));
        float sum = 0.0f;
        #pragma unroll 8
        for (int i = 0; i < 32; i++) {
            float e = expf(crow[i] - mx);
            crow[i] = e; sum += e;
        }
        sum += __shfl_xor_sync(0xffffffffu, sum, 1);
        float inv = 1.0f / sum;
        float* dst = g_kv + (size_t)(rowBase + r) * 1024 + blockIdx.y * 64 + half * 32;
        #pragma unroll 8
        for (int i = 0; i < 32; i++)
            dst[i] = crow[i] * inv * (crow[64 + i] + bvh_[i]);
    }
}

/* ---- stage A: P[b,h,jj,d] = sum_l F[l,jj]*kv[b,l,h,d]; 16 splits x 128 l ---- */
__global__ void __launch_bounds__(256) k_stageA() {
    const int bh = blockIdx.x, b = bh >> 4, h = bh & 15;
    const int lbase0 = blockIdx.y * 128;
    const int tid = threadIdx.x, tx = tid & 15, ty = tid >> 4;
    __shared__ __align__(16) float F[16][64];
    __shared__ __align__(16) float KV[16][64];
    float acc[4][4] = {};
    for (int sub = 0; sub < 8; sub++) {
        int lbase = lbase0 + sub * 16;
        *(float4*)&F[ty][tx*4]  = *(const float4*)(g_F + (size_t)(lbase + ty) * 64 + tx * 4);
        *(float4*)&KV[ty][tx*4] = *(const float4*)(g_kv + (size_t)(b * TT + lbase + ty) * DIMM + h * 64 + tx * 4);
        __syncthreads();
        #pragma unroll
        for (int l = 0; l < 16; l++) {
            float4 f4 = *(const float4*)&F[l][ty * 4];
            float4 k4 = *(const float4*)&KV[l][tx * 4];
            float ff[4] = {f4.x, f4.y, f4.z, f4.w};
            float kk[4] = {k4.x, k4.y, k4.z, k4.w};
            #pragma unroll
            for (int i = 0; i < 4; i++)
                #pragma unroll
                for (int j = 0; j < 4; j++) acc[i][j] += ff[i] * kk[j];
        }
        __syncthreads();
    }
    float* Pp = g_P + (size_t)bh * 4096;
    #pragma unroll
    for (int i = 0; i < 4; i++)
        #pragma unroll
        for (int j = 0; j < 4; j++)
            atomicAdd(&Pp[(ty*4 + i) * 64 + tx*4 + j], acc[i][j]);
}

/* ---- stage B: loading = G . P -> fp16 A; 64 t-rows x 64 d per block, 4 rows/thread ---- */
__global__ void __launch_bounds__(256) k_stageB() {
    const int base = blockIdx.x * 64;
    const int h = blockIdx.y;
    const int b = base / TT, t0 = base - b * TT;
    const int tid = threadIdx.x, tx = tid & 15, ty = tid >> 4;
    __shared__ __align__(16) float Ph[64][64];
    __shared__ __align__(16) float Gs[64][68];
    /* load P tile: 1024 float4 */
    {
        const float4* Psrc = (const float4*)(g_P + (size_t)(b * HH + h) * 4096);
        float4* Pd = (float4*)Ph;
        #pragma unroll
        for (int p = 0; p < 4; p++) Pd[tid + p * 256] = Psrc[tid + p * 256];
    }
    /* load G tile: 64 rows x 16 float4 */
    #pragma unroll
    for (int p = 0; p < 4; p++) {
        int e = tid + p * 256;
        int row = e >> 4, c4 = (e & 15) * 4;
        *(float4*)&Gs[row][c4] = *(const float4*)(g_G + (size_t)((t0 + row) * HH + h) * 64 + c4);
    }
    __syncthreads();
    float acc[4][4] = {};
    #pragma unroll
    for (int jj = 0; jj < 64; jj++) {
        float4 p = *(const float4*)&Ph[jj][tx * 4];
        #pragma unroll
        for (int i = 0; i < 4; i++) {
            float g = Gs[ty*4 + i][jj];
            acc[i][0] += g*p.x; acc[i][1] += g*p.y; acc[i][2] += g*p.z; acc[i][3] += g*p.w;
        }
    }
    #pragma unroll
    for (int i = 0; i < 4; i++) {
        int row = base + ty*4 + i;
        float4 o = make_float4(acc[i][0], acc[i][1], acc[i][2], acc[i][3]);
        store_h4(g_loads + (size_t)row * TKE + h * 64 + tx * 4, o);
    }
}

extern "C" void kernel_launch(void* const* d_in, const int* in_sizes, int n_in,
                              void* d_out, int out_size) {
    const float* states = (const float*)d_in[0];
    const int*   mask   = (const int*)  d_in[1];
    const float* lnw    = (const float*)d_in[2];
    const float* angles = (const float*)d_in[3];
    const float* hdelta = (const float*)d_in[4];
    const float* Wk = (const float*)d_in[7];
    const float* bk = (const float*)d_in[8];
    const float* Wv = (const float*)d_in[9];
    const float* bv = (const float*)d_in[10];
    const float* Wo = (const float*)d_in[11];
    const float* bo = (const float*)d_in[12];
    float* out = (float*)d_out;

    cudaFuncSetAttribute(k_mma, cudaFuncAttributeMaxDynamicSharedMemorySize, GSMEM);

    k_prep<<<9248, 256>>>(states, lnw, Wk, Wv, Wo, angles, hdelta);

    dim3 gkv(MM / 128, HH);
    k_mma<<<gkv, 256, GSMEM>>>(0, nullptr, nullptr, bk, bv, mask);

    dim3 ga(BB * HH, 16);
    k_stageA<<<ga, 256>>>();
    dim3 gb(MM / 64, HH);
    k_stageB<<<gb, 256>>>();

    dim3 go(MM / 128, DIMM / 128);
    k_mma<<<go, 256, GSMEM>>>(1, out, bo, nullptr, nullptr, nullptr);
}

// round 16
// speedup vs baseline: 1.6170x; 1.0002x over previous
#include <cuda_runtime.h>
#include <cuda_fp16.h>
#include <math.h>
#include <stdint.h>

#define BB 2
#define TT 2048
#define DIMM 1024
#define HH 16
#define MM (BB*TT)
#define TKE 1024
#define NCH 16
#define EPSF 1.1920928955078125e-07f
#define GSMEM (3*32768)
#define SMB2 (16384 + 128*68*4)   /* Ph 16KB + Gs[128][68] 34.8KB = 51200 B */

__device__ __align__(256) __half g_xs[(size_t)MM * TKE];
__device__ __align__(256) __half g_wkv[(size_t)2048 * TKE];  /* head-interleaved [k_h|v_h] */
__device__ __align__(256) __half g_wo[(size_t)1024 * TKE];
__device__ __align__(256) __half g_loads[(size_t)MM * TKE];
__device__ __align__(256) float g_kv[(size_t)MM * DIMM];
__device__ __align__(256) float g_F[TT * 64];
__device__ __align__(256) float g_G[TT * HH * 64];
__device__ __align__(256) float g_P[BB * HH * 64 * 64];

__device__ __forceinline__ uint32_t smem_u32(const void* p) {
    uint32_t a;
    asm("{ .reg .u64 t; cvta.to.shared.u64 t, %1; cvt.u32.u64 %0, t; }" : "=r"(a) : "l"(p));
    return a;
}
__device__ __forceinline__ void cpa16(uint32_t d, const void* s) {
    asm volatile("cp.async.cg.shared.global [%0], [%1], 16;" :: "r"(d), "l"(s));
}
/* fp32 Cody-Waite 2pi reduction: P1 products exact (n has <=8 mantissa bits) */
__device__ __forceinline__ void sincos_cw(float ang, float* s, float* c) {
    const float INV2PI = 0.15915494309189535f;
    const float P1 = 6.28125f;
    const float P2 = 1.9353071795864769e-3f;
    float n = rintf(ang * INV2PI);
    float r = fmaf(-n, P1, ang);
    r = fmaf(-n, P2, r);
    sincosf(r, s, c);
}
__device__ __forceinline__ void store_h4(__half* dst, float4 v) {
    __half2* d = (__half2*)dst;
    d[0] = __floats2half2_rn(v.x, v.y);
    d[1] = __floats2half2_rn(v.z, v.w);
}
__device__ __forceinline__ uint4 ldsm4(uint32_t a) {
    uint4 r;
    asm volatile("ldmatrix.sync.aligned.m8n8.x4.shared.b16 {%0,%1,%2,%3}, [%4];"
                 : "=r"(r.x), "=r"(r.y), "=r"(r.z), "=r"(r.w) : "r"(a));
    return r;
}
__device__ __forceinline__ void mma16816(float* c, uint4 a, uint32_t b0, uint32_t b1) {
    asm volatile("mma.sync.aligned.m16n8k16.row.col.f32.f16.f16.f32 "
                 "{%0,%1,%2,%3}, {%4,%5,%6,%7}, {%8,%9}, {%0,%1,%2,%3};"
                 : "+f"(c[0]), "+f"(c[1]), "+f"(c[2]), "+f"(c[3])
                 : "r"(a.x), "r"(a.y), "r"(a.z), "r"(a.w), "r"(b0), "r"(b1));
}

/* ---- fused prep: convw (0..3071) | trig (3072..5119) | rmsnorm (5120..9215) | zeroP (9216..9247) ---- */
__global__ void __launch_bounds__(256) k_prep(const float* __restrict__ states,
                                              const float* __restrict__ lnw,
                                              const float* __restrict__ Wk,
                                              const float* __restrict__ Wv,
                                              const float* __restrict__ Wo,
                                              const float* __restrict__ angles,
                                              const float* __restrict__ hdelta) {
    const int bid = blockIdx.x, tid = threadIdx.x;
    if (bid < 3072) {                                   /* weight conversion -> fp16 */
        int row = bid;
        const float* src; __half* dst;
        if (row < 2048) {
            int h = row >> 7, c = row & 127;
            src = (c < 64) ? Wk + (size_t)(h * 64 + c) * 1024
                           : Wv + (size_t)(h * 64 + c - 64) * 1024;
            dst = g_wkv + (size_t)row * TKE;
        } else {
            src = Wo + (size_t)(row - 2048) * 1024;
            dst = g_wo + (size_t)(row - 2048) * TKE;
        }
        float4 v = ((const float4*)src)[tid];
        store_h4(dst + tid * 4, v);
    } else if (bid < 5120) {                            /* trig tables */
        int t = bid - 3072;
        __shared__ float w[32], hd[16];
        if (tid < 32) w[tid] = angles[tid];
        if (tid >= 32 && tid < 48) hd[tid - 32] = hdelta[tid - 32];
        __syncthreads();
        if (tid < 32) {
            float s, c; sincos_cw((float)t * w[tid], &s, &c);
            g_F[t * 64 + tid] = c; g_F[t * 64 + 32 + tid] = s;
        }
        for (int e = tid; e < 512; e += 256) {
            int h = e >> 5, j = e & 31;
            float s, c; sincos_cw(((float)t + hd[h]) * w[j], &s, &c);
            g_G[(size_t)(t * HH + h) * 64 + j]      = c * 0.03125f;
            g_G[(size_t)(t * HH + h) * 64 + 32 + j] = s * 0.03125f;
        }
    } else if (bid < 9216) {                            /* RMSNorm -> fp16 A */
        int row = bid - 5120;
        float4 v = ((const float4*)(states + (size_t)row * DIMM))[tid];
        float ss = v.x*v.x + v.y*v.y + v.z*v.z + v.w*v.w;
        #pragma unroll
        for (int o = 16; o > 0; o >>= 1) ss += __shfl_xor_sync(0xffffffffu, ss, o);
        __shared__ float wsum[8];
        if ((tid & 31) == 0) wsum[tid >> 5] = ss;
        __syncthreads();
        if (tid < 8) {
            float s2 = wsum[tid];
            #pragma unroll
            for (int o = 4; o > 0; o >>= 1) s2 += __shfl_xor_sync(0xffu, s2, o);
            if (tid == 0) wsum[0] = s2;
        }
        __syncthreads();
        float sc = rsqrtf(wsum[0] * (1.0f / DIMM) + EPSF);
        float4 w = ((const float4*)lnw)[tid];
        float4 o = make_float4(v.x*sc*w.x, v.y*sc*w.y, v.z*sc*w.z, v.w*sc*w.w);
        store_h4(g_xs + (size_t)row * TKE + tid * 4, o);
    } else {                                            /* zero g_P: 32 blocks x 4096 floats */
        int base = (bid - 9216) * 4096 + tid * 4;
        float4 z = make_float4(0.f, 0.f, 0.f, 0.f);
        #pragma unroll
        for (int i = 0; i < 4; i++)
            *(float4*)(g_P + base + i * 1024) = z;
    }
}

/* ---- warp-MMA GEMM (fp16), single-sync pipeline; mode0 fuses softmax*v ---- */
__global__ void __launch_bounds__(256, 2) k_mma(int mode, float* __restrict__ outp,
                                                const float* __restrict__ bo,
                                                const float* __restrict__ bk,
                                                const float* __restrict__ bv,
                                                const int* __restrict__ mask) {
    extern __shared__ __align__(16) char smc[];
    __shared__ float bks[64], bvs[64];
    const __half* Ap = mode ? g_loads : g_xs;
    const __half* Bp = mode ? g_wo : g_wkv;
    const int tid = threadIdx.x;
    const int rowBase = blockIdx.x * 128, colBase = blockIdx.y * 128;
    uint32_t sb = smem_u32(smc);

    if (mode == 0) {
        if (tid < 64)            bks[tid]      = bk[blockIdx.y * 64 + tid];
        else if (tid < 128)      bvs[tid - 64] = bv[blockIdx.y * 64 + tid - 64];
    }

    const int lr = tid >> 1, lsg = (tid & 1) * 4;
    const __half* gA = Ap + (size_t)(rowBase + lr) * TKE + lsg * 8;
    const __half* gB = Bp + (size_t)(colBase + lr) * TKE + lsg * 8;
    uint32_t sw[4];
    #pragma unroll
    for (int s = 0; s < 4; s++) {
        uint32_t o = lr * 128 + (lsg + s) * 16;
        sw[s] = o ^ ((o >> 3) & 0x70);
    }
    #define LOADC(c) do {                                                         \
        uint32_t stA = sb + ((c) % 3) * 32768, stB = stA + 16384;                 \
        const __half* pa = gA + (size_t)(c) * 64;                                 \
        const __half* pb = gB + (size_t)(c) * 64;                                 \
        cpa16(stA + sw[0], pa);      cpa16(stB + sw[0], pb);                      \
        cpa16(stA + sw[1], pa + 8);  cpa16(stB + sw[1], pb + 8);                  \
        cpa16(stA + sw[2], pa + 16); cpa16(stB + sw[2], pb + 16);                 \
        cpa16(stA + sw[3], pa + 24); cpa16(stB + sw[3], pb + 24);                 \
        asm volatile("cp.async.commit_group;" ::: "memory"); } while (0)

    const int w = tid >> 5, lane = tid & 31;
    const int wm = w & 1, wn = w >> 1;
    const int arow = wm * 64 + ((lane >> 3) & 1) * 8 + (lane & 7);
    const uint32_t akh = (lane >> 4) * 16;
    const uint32_t aSwz = (arow & 7) * 16;
    uint32_t aOff[4];
    #pragma unroll
    for (int mt = 0; mt < 4; mt++) aOff[mt] = (arow + mt * 16) * 128;
    const int bn = wn * 32 + ((lane >> 4) & 1) * 8 + (lane & 7);
    const uint32_t bkh = ((lane >> 3) & 1) * 16;
    const uint32_t bSwz = (bn & 7) * 16;
    uint32_t bOff[2];
    bOff[0] = bn * 128; bOff[1] = (bn + 16) * 128;

    float acc[4][4][4];
    #pragma unroll
    for (int i = 0; i < 4; i++)
        #pragma unroll
        for (int j = 0; j < 4; j++)
            #pragma unroll
            for (int q = 0; q < 4; q++) acc[i][j][q] = 0.0f;

    uint4 Af[2][4]; uint4 Bf[2][2];
    #define LDFRAG(buf, stA, stB, ksv) do {                                       \
        uint32_t ka = ((ksv) * 32 + akh) ^ aSwz;                                  \
        uint32_t kb = ((ksv) * 32 + bkh) ^ bSwz;                                  \
        Af[buf][0] = ldsm4((stA) + aOff[0] + ka);                                 \
        Af[buf][1] = ldsm4((stA) + aOff[1] + ka);                                 \
        Af[buf][2] = ldsm4((stA) + aOff[2] + ka);                                 \
        Af[buf][3] = ldsm4((stA) + aOff[3] + ka);                                 \
        Bf[buf][0] = ldsm4((stB) + bOff[0] + kb);                                 \
        Bf[buf][1] = ldsm4((stB) + bOff[1] + kb); } while (0)

    /* single-sync pipeline: prefetch distance 2, one barrier per chunk */
    LOADC(0); LOADC(1);
    for (int j = 0; j < NCH; j++) {
        if (j < NCH - 1) asm volatile("cp.async.wait_group 1;" ::: "memory");
        else             asm volatile("cp.async.wait_group 0;" ::: "memory");
        __syncthreads();
        uint32_t stA = sb + (j % 3) * 32768, stB = stA + 16384;
        if (j + 2 < NCH) LOADC(j + 2);   /* writes stage (j-1)%3: consumed last iter */
        LDFRAG(0, stA, stB, 0);
        #pragma unroll
        for (int ks = 0; ks < 4; ks++) {
            if (ks < 3) LDFRAG((ks + 1) & 1, stA, stB, ks + 1);
            const int cb = ks & 1;
            uint32_t bb[4][2] = {{Bf[cb][0].x, Bf[cb][0].y}, {Bf[cb][0].z, Bf[cb][0].w},
                                 {Bf[cb][1].x, Bf[cb][1].y}, {Bf[cb][1].z, Bf[cb][1].w}};
            #pragma unroll
            for (int mt = 0; mt < 4; mt++)
                #pragma unroll
                for (int nt = 0; nt < 4; nt++)
                    mma16816(acc[mt][nt], Af[cb][mt], bb[nt][0], bb[nt][1]);
        }
    }
    #undef LOADC
    #undef LDFRAG

    if (mode == 1) {
        const int crow0 = rowBase + wm * 64 + (lane >> 2);
        const int ccol0 = colBase + wn * 32 + (lane & 3) * 2;
        #pragma unroll
        for (int mt = 0; mt < 4; mt++) {
            #pragma unroll
            for (int nt = 0; nt < 4; nt++) {
                int row = crow0 + mt * 16, col = ccol0 + nt * 8;
                float b0 = bo[col], b1 = bo[col + 1];
                float2 v0 = make_float2(acc[mt][nt][0] + b0, acc[mt][nt][1] + b1);
                float2 v1 = make_float2(acc[mt][nt][2] + b0, acc[mt][nt][3] + b1);
                *(float2*)(outp + (size_t)row * 1024 + col) = v0;
                *(float2*)(outp + (size_t)(row + 8) * 1024 + col) = v1;
            }
        }
        return;
    }

    /* mode 0: stage scores to smem, per-row softmax(k)*v -> g_kv */
    __syncthreads();   /* all warps done with smem stages before reuse as Cs */
    float* Cs = (float*)smc;                  /* stride 129: conflict-free */
    const int lrow0 = wm * 64 + (lane >> 2);
    const int lcol0 = wn * 32 + (lane & 3) * 2;
    #pragma unroll
    for (int mt = 0; mt < 4; mt++) {
        #pragma unroll
        for (int nt = 0; nt < 4; nt++) {
            int rr = lrow0 + mt * 16, cc = lcol0 + nt * 8;
            Cs[rr * 129 + cc]           = acc[mt][nt][0];
            Cs[rr * 129 + cc + 1]       = acc[mt][nt][1];
            Cs[(rr + 8) * 129 + cc]     = acc[mt][nt][2];
            Cs[(rr + 8) * 129 + cc + 1] = acc[mt][nt][3];
        }
    }
    __syncthreads();
    {
        const int r = tid >> 1, half = tid & 1;
        float m = (float)mask[rowBase + r];
        float* crow = Cs + r * 129 + half * 32;       /* k: crow[0..31], v: crow[64..95] */
        const float* bkh_ = bks + half * 32;
        const float* bvh_ = bvs + half * 32;
        float mx = -INFINITY;
        #pragma unroll 8
        for (int i = 0; i < 32; i++) {
            float kk = (crow[i] + bkh_[i]) * m;
            crow[i] = kk; mx = fmaxf(mx, kk);
        }
        mx = fmaxf(mx, __shfl_xor_sync(0xffffffffu, mx, 1));
        float sum = 0.0f;
        #pragma unroll 8
        for (int i = 0; i < 32; i++) {
            float e = expf(crow[i] - mx);
            crow[i] = e; sum += e;
        }
        sum += __shfl_xor_sync(0xffffffffu, sum, 1);
        float inv = 1.0f / sum;
        float* dst = g_kv + (size_t)(rowBase + r) * 1024 + blockIdx.y * 64 + half * 32;
        #pragma unroll 8
        for (int i = 0; i < 32; i++)
            dst[i] = crow[i] * inv * (crow[64 + i] + bvh_[i]);
    }
}

/* ---- stage A: P[b,h,jj,d] = sum_l F[l,jj]*kv[b,l,h,d]; 16 splits x 128 l ---- */
__global__ void __launch_bounds__(256) k_stageA() {
    const int bh = blockIdx.x, b = bh >> 4, h = bh & 15;
    const int lbase0 = blockIdx.y * 128;
    const int tid = threadIdx.x, tx = tid & 15, ty = tid >> 4;
    __shared__ __align__(16) float F[16][64];
    __shared__ __align__(16) float KV[16][64];
    float acc[4][4] = {};
    for (int sub = 0; sub < 8; sub++) {
        int lbase = lbase0 + sub * 16;
        *(float4*)&F[ty][tx*4]  = *(const float4*)(g_F + (size_t)(lbase + ty) * 64 + tx * 4);
        *(float4*)&KV[ty][tx*4] = *(const float4*)(g_kv + (size_t)(b * TT + lbase + ty) * DIMM + h * 64 + tx * 4);
        __syncthreads();
        #pragma unroll
        for (int l = 0; l < 16; l++) {
            float4 f4 = *(const float4*)&F[l][ty * 4];
            float4 k4 = *(const float4*)&KV[l][tx * 4];
            float ff[4] = {f4.x, f4.y, f4.z, f4.w};
            float kk[4] = {k4.x, k4.y, k4.z, k4.w};
            #pragma unroll
            for (int i = 0; i < 4; i++)
                #pragma unroll
                for (int j = 0; j < 4; j++) acc[i][j] += ff[i] * kk[j];
        }
        __syncthreads();
    }
    float* Pp = g_P + (size_t)bh * 4096;
    #pragma unroll
    for (int i = 0; i < 4; i++)
        #pragma unroll
        for (int j = 0; j < 4; j++)
            atomicAdd(&Pp[(ty*4 + i) * 64 + tx*4 + j], acc[i][j]);
}

/* ---- stage B: loading = G . P -> fp16 A; 128 t-rows x 64 d per block, 8 rows/thread ---- */
__global__ void __launch_bounds__(256) k_stageB() {
    extern __shared__ __align__(16) float smb2[];   /* Ph[64*64] then Gs[128*68] */
    const int base = blockIdx.x * 128;
    const int h = blockIdx.y;
    const int b = base / TT, t0 = base - b * TT;
    const int tid = threadIdx.x, tx = tid & 15, ty = tid >> 4;
    float* Ph = smb2;
    float* Gs = smb2 + 4096;
    /* load P tile: 1024 float4 */
    {
        const float4* Psrc = (const float4*)(g_P + (size_t)(b * HH + h) * 4096);
        float4* Pd = (float4*)Ph;
        #pragma unroll
        for (int p = 0; p < 4; p++) Pd[tid + p * 256] = Psrc[tid + p * 256];
    }
    /* load G tile: 128 rows x 16 float4 */
    #pragma unroll
    for (int p = 0; p < 8; p++) {
        int e = tid + p * 256;
        int row = e >> 4, c4 = (e & 15) * 4;
        *(float4*)&Gs[row * 68 + c4] = *(const float4*)(g_G + (size_t)((t0 + row) * HH + h) * 64 + c4);
    }
    __syncthreads();
    float acc[8][4] = {};
    #pragma unroll
    for (int jj = 0; jj < 64; jj++) {
        float4 p = *(const float4*)&Ph[jj * 64 + tx * 4];
        #pragma unroll
        for (int i = 0; i < 8; i++) {
            float g = Gs[(ty*8 + i) * 68 + jj];
            acc[i][0] += g*p.x; acc[i][1] += g*p.y; acc[i][2] += g*p.z; acc[i][3] += g*p.w;
        }
    }
    #pragma unroll
    for (int i = 0; i < 8; i++) {
        int row = base + ty*8 + i;
        float4 o = make_float4(acc[i][0], acc[i][1], acc[i][2], acc[i][3]);
        store_h4(g_loads + (size_t)row * TKE + h * 64 + tx * 4, o);
    }
}

extern "C" void kernel_launch(void* const* d_in, const int* in_sizes, int n_in,
                              void* d_out, int out_size) {
    const float* states = (const float*)d_in[0];
    const int*   mask   = (const int*)  d_in[1];
    const float* lnw    = (const float*)d_in[2];
    const float* angles = (const float*)d_in[3];
    const float* hdelta = (const float*)d_in[4];
    const float* Wk = (const float*)d_in[7];
    const float* bk = (const float*)d_in[8];
    const float* Wv = (const float*)d_in[9];
    const float* bv = (const float*)d_in[10];
    const float* Wo = (const float*)d_in[11];
    const float* bo = (const float*)d_in[12];
    float* out = (float*)d_out;

    cudaFuncSetAttribute(k_mma, cudaFuncAttributeMaxDynamicSharedMemorySize, GSMEM);
    cudaFuncSetAttribute(k_stageB, cudaFuncAttributeMaxDynamicSharedMemorySize, SMB2);

    k_prep<<<9248, 256>>>(states, lnw, Wk, Wv, Wo, angles, hdelta);

    dim3 gkv(MM / 128, HH);
    k_mma<<<gkv, 256, GSMEM>>>(0, nullptr, nullptr, bk, bv, mask);

    dim3 ga(BB * HH, 16);
    k_stageA<<<ga, 256>>>();
    dim3 gb(MM / 128, HH);
    k_stageB<<<gb, 256, SMB2>>>();

    dim3 go(MM / 128, DIMM / 128);
    k_mma<<<go, 256, GSMEM>>>(1, out, bo, nullptr, nullptr, nullptr);
}